// round 11
// baseline (speedup 1.0000x reference)
#include <cuda_runtime.h>
#include <cuda_bf16.h>
#include <math.h>
#include <stdint.h>

#define N_NODES 50000
#define N_EDGES 800000
#define ET (N_EDGES + N_NODES)
#define HEADS 4
#define OUT_CH 32
#define TOPK 8
#define NPAIRS (N_NODES * HEADS)
#define NB_SCAN ((N_NODES + 1023) / 1024)
typedef unsigned long long ull;

// ---------------- scratch ----------------
__device__ __align__(16) float g_h[N_NODES * 128];           // 25.6 MB
__device__ __align__(16) float g_si[NPAIRS];
__device__ __align__(16) uint32_t g_usk[NPAIRS];             // monotone(sj) keys
__device__ int   g_deg[N_NODES + 1];     // .bss zero; reset by scan1 each run
__device__ int   g_off[N_NODES + 1];
__device__ int   g_cur[N_NODES];
__device__ int   g_col[ET];
__device__ int   g_bsum[NB_SCAN + 1];
__device__ __align__(16) __nv_bfloat16 g_wth[128 * 128];     // W^T hi [n][k]
__device__ __align__(16) __nv_bfloat16 g_wtl[128 * 128];     // W^T lo [n][k]
__device__ __align__(16) float g_a2[128 * 8];                // W @ att combos

// ---------------- prep ----------------
__global__ void k_prep(const float* __restrict__ W, const float* __restrict__ att) {
    int t = blockIdx.x * blockDim.x + threadIdx.x;
    if (t < 16384) {
        int n = t >> 7, k = t & 127;
        float w = W[k * 128 + n];
        __nv_bfloat16 hi = __float2bfloat16(w);
        float lo = w - __bfloat162float(hi);
        g_wth[n * 128 + k] = hi;
        g_wtl[n * 128 + k] = __float2bfloat16(lo);
    }
    if (t < 1024) {
        int k = t >> 3, j = t & 7;
        int h = j & 3, part = j >> 2;
        float s = 0.f;
        #pragma unroll
        for (int c = 0; c < 32; c++)
            s += W[k * 128 + h * 32 + c] * att[h * 64 + part * 32 + c];
        g_a2[k * 8 + j] = s;
    }
}

// ---------------- CSR build ----------------
__global__ void k_hist(const int* __restrict__ ei) {
    int e = (blockIdx.x * blockDim.x + threadIdx.x) * 4;
    if (e < N_EDGES) {
        int4 v = *(const int4*)&ei[e];
        atomicAdd(&g_deg[v.x], 1);
        atomicAdd(&g_deg[v.y], 1);
        atomicAdd(&g_deg[v.z], 1);
        atomicAdd(&g_deg[v.w], 1);
    }
}

__global__ void k_scan1() {
    __shared__ int wsum[32];
    int tid = threadIdx.x;
    int lane = tid & 31, w = tid >> 5;
    int i = blockIdx.x * 1024 + tid;
    int v = 0;
    if (i < N_NODES) {
        v = g_deg[i] + 1;       // +1 self-loop
        g_deg[i] = 0;           // reset for next graph replay
        g_cur[i] = 0;
    }
    int s = v;
    #pragma unroll
    for (int o = 1; o < 32; o <<= 1) {
        int t = __shfl_up_sync(0xffffffffu, s, o);
        if (lane >= o) s += t;
    }
    if (lane == 31) wsum[w] = s;
    __syncthreads();
    if (w == 0) {
        int t = wsum[lane];
        #pragma unroll
        for (int o = 1; o < 32; o <<= 1) {
            int u = __shfl_up_sync(0xffffffffu, t, o);
            if (lane >= o) t += u;
        }
        wsum[lane] = t;
        if (lane == 31) g_bsum[blockIdx.x] = t;
    }
    __syncthreads();
    int carry = (w > 0) ? wsum[w - 1] : 0;
    if (i < N_NODES) g_off[i] = s - v + carry;
}

__global__ void k_scan3() {
    __shared__ int carry;
    int tid = threadIdx.x;
    if (tid < 32) {
        int s = 0;
        for (int b = tid; b < blockIdx.x; b += 32) s += g_bsum[b];
        #pragma unroll
        for (int o = 16; o; o >>= 1) s += __shfl_xor_sync(0xffffffffu, s, o);
        if (tid == 0) carry = s;
    }
    __syncthreads();
    int i = blockIdx.x * 1024 + tid;
    if (i < N_NODES) g_off[i] += carry;
    if (i == 0) g_off[N_NODES] = ET;
}

__global__ void k_scatter(const int* __restrict__ ei) {
    int idx = blockIdx.x * blockDim.x + threadIdx.x;
    if (idx >= ET) return;
    int r, c;
    if (idx < N_EDGES) { r = ei[idx]; c = ei[N_EDGES + idx]; }
    else               { r = idx - N_EDGES; c = r; }
    int p = g_off[r] + atomicAdd(&g_cur[r], 1);
    g_col[p] = c;
}

// ---------------- scores: warp/node, A2 in regs, 2-shuffle reduce ----------
// lane: j = lane>>2 (output combo), chunk = lane&3 (k-chunk of 32)
__global__ void __launch_bounds__(256) k_scores(const float* __restrict__ x) {
    __shared__ float srow[8][132];
    int tid = threadIdx.x;
    int w = tid >> 5, lane = tid & 31;
    int j = lane >> 2, rot = lane & 3;

    // A2 chunk in registers, stored pre-rotated to keep register indices static
    float4 areg[8];
    #pragma unroll
    for (int i = 0; i < 8; i++) {
        int kb = rot * 32 + ((i + 2 * rot) & 7) * 4;
        areg[i].x = g_a2[(kb + 0) * 8 + j];
        areg[i].y = g_a2[(kb + 1) * 8 + j];
        areg[i].z = g_a2[(kb + 2) * 8 + j];
        areg[i].w = g_a2[(kb + 3) * 8 + j];
    }

    int base = (blockIdx.x * 8 + w) * 8;
    #pragma unroll
    for (int n = 0; n < 8; n++) {
        int node = base + n;
        if (node >= N_NODES) break;
        float4 xv = *(const float4*)&x[node * 128 + lane * 4];
        *(float4*)&srow[w][lane * 4] = xv;
        __syncwarp();
        float acc = 0.f;
        #pragma unroll
        for (int i = 0; i < 8; i++) {
            const float4 v = *(const float4*)&srow[w][rot * 32 + ((i + 2 * rot) & 7) * 4];
            acc += v.x * areg[i].x + v.y * areg[i].y + v.z * areg[i].z + v.w * areg[i].w;
        }
        acc += __shfl_xor_sync(0xffffffffu, acc, 1);
        acc += __shfl_xor_sync(0xffffffffu, acc, 2);
        if (rot == 0) {
            if (j < 4) {
                g_si[node * 4 + j] = acc;
            } else {
                unsigned u = __float_as_uint(acc);
                u ^= (unsigned)((int)u >> 31) | 0x80000000u;   // monotone map
                g_usk[node * 4 + (j - 4)] = u;
            }
        }
        __syncwarp();
    }
}

// ---------------- GEMM: mma.sync bf16 3-term split + ldmatrix --------------
#define KP 40

__device__ __forceinline__ void hmma(float* c, const uint32_t* a,
                                     uint32_t b0, uint32_t b1) {
    asm volatile(
        "mma.sync.aligned.m16n8k16.row.col.f32.bf16.bf16.f32 "
        "{%0,%1,%2,%3}, {%4,%5,%6,%7}, {%8,%9}, {%0,%1,%2,%3};"
        : "+f"(c[0]), "+f"(c[1]), "+f"(c[2]), "+f"(c[3])
        : "r"(a[0]), "r"(a[1]), "r"(a[2]), "r"(a[3]), "r"(b0), "r"(b1));
}

#define LDSM4(R, addr) \
    asm volatile("ldmatrix.sync.aligned.m8n8.x4.shared.b16 {%0,%1,%2,%3}, [%4];" \
        : "=r"((R)[0]), "=r"((R)[1]), "=r"((R)[2]), "=r"((R)[3]) : "r"(addr))

__global__ void __launch_bounds__(256, 2)
k_gemm(const float* __restrict__ x) {
    __shared__ __nv_bfloat16 sAh[128][KP];
    __shared__ __nv_bfloat16 sAl[128][KP];
    __shared__ __nv_bfloat16 sBh[128][KP];
    __shared__ __nv_bfloat16 sBl[128][KP];

    int tid = threadIdx.x;
    int wid = tid >> 5, lane = tid & 31;
    int m0 = blockIdx.x * 128;
    int rb = (wid & 3) * 32;
    int nb = (wid >> 2) * 64;

    float acc[2][8][4];
    #pragma unroll
    for (int mt = 0; mt < 2; mt++)
        #pragma unroll
        for (int nt = 0; nt < 8; nt++)
            #pragma unroll
            for (int q = 0; q < 4; q++) acc[mt][nt][q] = 0.f;

    int tsub = lane >> 3;
    int trow = lane & 7;

    for (int st = 0; st < 4; st++) {
        int k0 = st * 32;
        #pragma unroll
        for (int it = 0; it < 2; it++) {
            int idx = tid + it * 256;
            int row = idx >> 2;
            int c0 = (idx & 3) * 8;
            int rr = m0 + row;
            float4 v0 = make_float4(0.f, 0.f, 0.f, 0.f), v1 = v0;
            if (rr < N_NODES) {
                v0 = *(const float4*)&x[rr * 128 + k0 + c0];
                v1 = *(const float4*)&x[rr * 128 + k0 + c0 + 4];
            }
            float vs[8] = {v0.x, v0.y, v0.z, v0.w, v1.x, v1.y, v1.z, v1.w};
            uint32_t hw[4], lw[4];
            #pragma unroll
            for (int q = 0; q < 4; q++) {
                __nv_bfloat16 h0 = __float2bfloat16(vs[2 * q]);
                __nv_bfloat16 h1 = __float2bfloat16(vs[2 * q + 1]);
                float l0 = vs[2 * q] - __bfloat162float(h0);
                float l1 = vs[2 * q + 1] - __bfloat162float(h1);
                hw[q] = (uint32_t)__bfloat16_as_ushort(h0) |
                        ((uint32_t)__bfloat16_as_ushort(h1) << 16);
                lw[q] = (uint32_t)__bfloat16_as_ushort(__float2bfloat16(l0)) |
                        ((uint32_t)__bfloat16_as_ushort(__float2bfloat16(l1)) << 16);
            }
            *(uint4*)&sAh[row][c0] = make_uint4(hw[0], hw[1], hw[2], hw[3]);
            *(uint4*)&sAl[row][c0] = make_uint4(lw[0], lw[1], lw[2], lw[3]);
            *(uint4*)&sBh[row][c0] = *(const uint4*)&g_wth[row * 128 + k0 + c0];
            *(uint4*)&sBl[row][c0] = *(const uint4*)&g_wtl[row * 128 + k0 + c0];
        }
        __syncthreads();

        #pragma unroll
        for (int ks = 0; ks < 2; ks++) {
            int ck = ks * 16;
            uint32_t Ah[2][4], Al[2][4];
            #pragma unroll
            for (int mt = 0; mt < 2; mt++) {
                int r = rb + mt * 16 + ((tsub & 1) << 3) + trow;
                int c = ck + ((tsub >> 1) << 3);
                LDSM4(Ah[mt], (uint32_t)__cvta_generic_to_shared(&sAh[r][c]));
                LDSM4(Al[mt], (uint32_t)__cvta_generic_to_shared(&sAl[r][c]));
            }
            #pragma unroll
            for (int np = 0; np < 4; np++) {
                int n = nb + np * 16 + ((tsub >> 1) << 3) + trow;
                int c = ck + ((tsub & 1) << 3);
                uint32_t Bh[4], Bl[4];
                LDSM4(Bh, (uint32_t)__cvta_generic_to_shared(&sBh[n][c]));
                LDSM4(Bl, (uint32_t)__cvta_generic_to_shared(&sBl[n][c]));
                #pragma unroll
                for (int mt = 0; mt < 2; mt++) {
                    hmma(acc[mt][2 * np],     Ah[mt], Bh[0], Bh[1]);
                    hmma(acc[mt][2 * np],     Ah[mt], Bl[0], Bl[1]);
                    hmma(acc[mt][2 * np],     Al[mt], Bh[0], Bh[1]);
                    hmma(acc[mt][2 * np + 1], Ah[mt], Bh[2], Bh[3]);
                    hmma(acc[mt][2 * np + 1], Ah[mt], Bl[2], Bl[3]);
                    hmma(acc[mt][2 * np + 1], Al[mt], Bh[2], Bh[3]);
                }
            }
        }
        __syncthreads();
    }

    #pragma unroll
    for (int mt = 0; mt < 2; mt++) {
        int r0 = m0 + rb + mt * 16 + (lane >> 2);
        #pragma unroll
        for (int nt = 0; nt < 8; nt++) {
            int col = nb + nt * 8 + (lane & 3) * 2;
            if (r0 < N_NODES)
                *(float2*)&g_h[r0 * 128 + col] =
                    make_float2(acc[mt][nt][0], acc[mt][nt][1]);
            if (r0 + 8 < N_NODES)
                *(float2*)&g_h[(r0 + 8) * 128 + col] =
                    make_float2(acc[mt][nt][2], acc[mt][nt][3]);
        }
    }
}

// ---------------- fused top-k (4 heads/thread) + softmax + aggregate -------
#define TB 128
#define CS(h, a, b) { ull _x = key[h][a], _y = key[h][b]; \
                      key[h][a] = (_x > _y) ? _x : _y; key[h][b] = (_x > _y) ? _y : _x; }
#define BUB(h) { CS(h,6,7) CS(h,5,6) CS(h,4,5) CS(h,3,4) CS(h,2,3) CS(h,1,2) CS(h,0,1) }
#define INS(h, uu, cc) { ull _k = ((ull)(uu) << 32) | (unsigned)(cc); \
                         if (_k > key[h][7]) { key[h][7] = _k; BUB(h) } }

__global__ void __launch_bounds__(TB) k_topkagg(float* __restrict__ out) {
    __shared__ float salpha[TB * 4][TOPK];
    __shared__ int   scol[TB * 4][TOPK];

    int tid = threadIdx.x;
    int node0 = blockIdx.x * TB;

    // ---- phase 1: thread per node, all 4 heads fused
    {
        int node = node0 + tid;
        if (node < N_NODES) {
            int start = g_off[node];
            int end   = g_off[node + 1];
            int deg = end - start;

            ull key[4][8];
            #pragma unroll
            for (int h = 0; h < 4; h++)
                #pragma unroll
                for (int r = 0; r < 8; r++) key[h][r] = 0ull;

            int i = start;
            for (; i + 1 < end; i += 2) {
                int c0 = g_col[i], c1 = g_col[i + 1];
                uint4 u0 = *(const uint4*)&g_usk[c0 * 4];
                uint4 u1 = *(const uint4*)&g_usk[c1 * 4];
                INS(0, u0.x, c0) INS(1, u0.y, c0) INS(2, u0.z, c0) INS(3, u0.w, c0)
                INS(0, u1.x, c1) INS(1, u1.y, c1) INS(2, u1.z, c1) INS(3, u1.w, c1)
            }
            if (i < end) {
                int c = g_col[i];
                uint4 u = *(const uint4*)&g_usk[c * 4];
                INS(0, u.x, c) INS(1, u.y, c) INS(2, u.z, c) INS(3, u.w, c)
            }

            int k = min(deg, TOPK);
            float4 si4 = *(const float4*)&g_si[node * 4];
            #pragma unroll
            for (int h = 0; h < 4; h++) {
                float si = (h == 0) ? si4.x : (h == 1) ? si4.y :
                           (h == 2) ? si4.z : si4.w;
                float sc[8];
                #pragma unroll
                for (int r = 0; r < 8; r++) {
                    unsigned u = (unsigned)(key[h][r] >> 32);
                    u ^= (~((unsigned)((int)u >> 31))) | 0x80000000u;  // inverse
                    float s = si + __uint_as_float(u);
                    sc[r] = (s > 0.f) ? s : 0.2f * s;                  // leaky
                }
                float maxe = sc[0];
                float p[8];
                float sum = 0.f;
                #pragma unroll
                for (int r = 0; r < 8; r++) {
                    float e = (r < k) ? __expf(sc[r] - maxe) : 0.f;
                    p[r] = e;
                    sum += e;
                }
                float inv = 1.f / sum;
                int lp = tid * 4 + h;
                #pragma unroll
                for (int r = 0; r < 8; r++) {
                    salpha[lp][r] = p[r] * inv;
                    scol[lp][r]   = (int)(unsigned)(key[h][r] & 0xffffffffull);
                }
            }
        } else {
            #pragma unroll
            for (int h = 0; h < 4; h++)
                #pragma unroll
                for (int r = 0; r < 8; r++) {
                    salpha[tid * 4 + h][r] = 0.f;
                    scol[tid * 4 + h][r] = 0;
                }
        }
    }
    __syncthreads();

    // ---- phase 2: warp per pair (4 warps, stride 4)
    int wid = tid >> 5, lane = tid & 31;
    for (int p = wid; p < TB * 4; p += 4) {
        int nd = node0 + (p >> 2);
        if (nd >= N_NODES) break;
        int head = p & 3;
        float acc = 0.f;
        #pragma unroll
        for (int r = 0; r < TOPK; r++) {
            float a = salpha[p][r];
            int   c = scol[p][r];
            acc += a * __ldg(&g_h[c * 128 + head * OUT_CH + lane]);
        }
        out[nd * 128 + head * OUT_CH + lane] = (acc > 0.f) ? acc : expm1f(acc);
    }
}

// ---------------- launch (slot 3 = new k_scores for ncu) --------------------
extern "C" void kernel_launch(void* const* d_in, const int* in_sizes, int n_in,
                              void* d_out, int out_size) {
    const float* x   = (const float*)d_in[0];
    const float* W   = (const float*)d_in[1];
    const float* att = (const float*)d_in[2];
    const int*   ei  = (const int*)d_in[3];
    float* out = (float*)d_out;

    k_prep<<<64, 256>>>(W, att);                                    // 0
    k_hist<<<(N_EDGES / 4 + 255) / 256, 256>>>(ei);                 // 1
    k_scan1<<<NB_SCAN, 1024>>>();                                   // 2
    k_scores<<<(N_NODES + 63) / 64, 256>>>(x);                      // 3 (profiled)
    k_gemm<<<(N_NODES + 127) / 128, 256>>>(x);                      // 4
    k_scan3<<<NB_SCAN, 1024>>>();                                   // 5
    k_scatter<<<(ET + 255) / 256, 256>>>(ei);                       // 6
    k_topkagg<<<(N_NODES + TB - 1) / TB, TB>>>(out);                // 7
}

// round 12
// speedup vs baseline: 1.3601x; 1.3601x over previous
#include <cuda_runtime.h>
#include <cuda_bf16.h>
#include <math.h>
#include <stdint.h>

#define N_NODES 50000
#define N_EDGES 800000
#define ET (N_EDGES + N_NODES)
#define HEADS 4
#define OUT_CH 32
#define TOPK 8
#define NPAIRS (N_NODES * HEADS)
#define NB_SCAN ((N_NODES + 1023) / 1024)
typedef unsigned long long ull;

// ---------------- scratch ----------------
__device__ __align__(16) float g_h[N_NODES * 128];           // 25.6 MB
__device__ __align__(16) float g_si[NPAIRS];
__device__ __align__(16) uint32_t g_usk[NPAIRS];             // monotone(sj) keys
__device__ int   g_deg[N_NODES + 1];     // .bss zero; reset by scan1 each run
__device__ int   g_off[N_NODES + 1];
__device__ int   g_cur[N_NODES];
__device__ int   g_col[ET];
__device__ int   g_bsum[NB_SCAN + 1];
__device__ __align__(16) __nv_bfloat16 g_wth[128 * 128];     // W^T hi [n][k]
__device__ __align__(16) __nv_bfloat16 g_wtl[128 * 128];     // W^T lo [n][k]
__device__ __align__(16) float g_a2[128 * 8];                // W @ att combos

// ---------------- prep ----------------
__global__ void k_prep(const float* __restrict__ W, const float* __restrict__ att) {
    int t = blockIdx.x * blockDim.x + threadIdx.x;
    if (t < 16384) {
        int n = t >> 7, k = t & 127;
        float w = W[k * 128 + n];
        __nv_bfloat16 hi = __float2bfloat16(w);
        float lo = w - __bfloat162float(hi);
        g_wth[n * 128 + k] = hi;
        g_wtl[n * 128 + k] = __float2bfloat16(lo);
    }
    if (t < 1024) {
        int k = t >> 3, j = t & 7;
        int h = j & 3, part = j >> 2;
        float s = 0.f;
        #pragma unroll
        for (int c = 0; c < 32; c++)
            s += W[k * 128 + h * 32 + c] * att[h * 64 + part * 32 + c];
        g_a2[k * 8 + j] = s;
    }
}

// ---------------- CSR build ----------------
__global__ void k_hist(const int* __restrict__ ei) {
    int e = (blockIdx.x * blockDim.x + threadIdx.x) * 4;
    if (e < N_EDGES) {
        int4 v = *(const int4*)&ei[e];
        atomicAdd(&g_deg[v.x], 1);
        atomicAdd(&g_deg[v.y], 1);
        atomicAdd(&g_deg[v.z], 1);
        atomicAdd(&g_deg[v.w], 1);
    }
}

__global__ void k_scan1() {
    __shared__ int wsum[32];
    int tid = threadIdx.x;
    int lane = tid & 31, w = tid >> 5;
    int i = blockIdx.x * 1024 + tid;
    int v = 0;
    if (i < N_NODES) {
        v = g_deg[i] + 1;       // +1 self-loop
        g_deg[i] = 0;           // reset for next graph replay
        g_cur[i] = 0;
    }
    int s = v;
    #pragma unroll
    for (int o = 1; o < 32; o <<= 1) {
        int t = __shfl_up_sync(0xffffffffu, s, o);
        if (lane >= o) s += t;
    }
    if (lane == 31) wsum[w] = s;
    __syncthreads();
    if (w == 0) {
        int t = wsum[lane];
        #pragma unroll
        for (int o = 1; o < 32; o <<= 1) {
            int u = __shfl_up_sync(0xffffffffu, t, o);
            if (lane >= o) t += u;
        }
        wsum[lane] = t;
        if (lane == 31) g_bsum[blockIdx.x] = t;
    }
    __syncthreads();
    int carry = (w > 0) ? wsum[w - 1] : 0;
    if (i < N_NODES) g_off[i] = s - v + carry;
}

__global__ void k_scan3() {
    __shared__ int carry;
    int tid = threadIdx.x;
    if (tid < 32) {
        int s = 0;
        for (int b = tid; b < blockIdx.x; b += 32) s += g_bsum[b];
        #pragma unroll
        for (int o = 16; o; o >>= 1) s += __shfl_xor_sync(0xffffffffu, s, o);
        if (tid == 0) carry = s;
    }
    __syncthreads();
    int i = blockIdx.x * 1024 + tid;
    if (i < N_NODES) g_off[i] += carry;
    if (i == 0) g_off[N_NODES] = ET;
}

__global__ void k_scatter(const int* __restrict__ ei) {
    int idx = blockIdx.x * blockDim.x + threadIdx.x;
    if (idx >= ET) return;
    int r, c;
    if (idx < N_EDGES) { r = ei[idx]; c = ei[N_EDGES + idx]; }
    else               { r = idx - N_EDGES; c = r; }
    int p = g_off[r] + atomicAdd(&g_cur[r], 1);
    g_col[p] = c;
}

// ---------------- scores: warp/8-nodes, prefetch 8 rows (MLP=8) ------------
__global__ void __launch_bounds__(256) k_scores(const float* __restrict__ x) {
    __shared__ float srow[8][132];
    int tid = threadIdx.x;
    int w = tid >> 5, lane = tid & 31;
    int j = lane >> 2, rot = lane & 3;

    // A2 chunk in registers, pre-rotated so register indices stay static
    float4 areg[8];
    #pragma unroll
    for (int i = 0; i < 8; i++) {
        int kb = rot * 32 + ((i + 2 * rot) & 7) * 4;
        areg[i].x = g_a2[(kb + 0) * 8 + j];
        areg[i].y = g_a2[(kb + 1) * 8 + j];
        areg[i].z = g_a2[(kb + 2) * 8 + j];
        areg[i].w = g_a2[(kb + 3) * 8 + j];
    }

    int base = (blockIdx.x * 8 + w) * 8;

    // prefetch all 8 node rows (8 independent LDG.128 in flight)
    float4 xv[8];
    #pragma unroll
    for (int n = 0; n < 8; n++) {
        int node = base + n;
        xv[n] = (node < N_NODES) ? *(const float4*)&x[node * 128 + lane * 4]
                                 : make_float4(0.f, 0.f, 0.f, 0.f);
    }

    #pragma unroll
    for (int n = 0; n < 8; n++) {
        int node = base + n;
        if (node >= N_NODES) break;
        *(float4*)&srow[w][lane * 4] = xv[n];
        __syncwarp();
        float acc = 0.f;
        #pragma unroll
        for (int i = 0; i < 8; i++) {
            const float4 v = *(const float4*)&srow[w][rot * 32 + ((i + 2 * rot) & 7) * 4];
            acc += v.x * areg[i].x + v.y * areg[i].y + v.z * areg[i].z + v.w * areg[i].w;
        }
        acc += __shfl_xor_sync(0xffffffffu, acc, 1);
        acc += __shfl_xor_sync(0xffffffffu, acc, 2);
        if (rot == 0) {
            if (j < 4) {
                g_si[node * 4 + j] = acc;
            } else {
                unsigned u = __float_as_uint(acc);
                u ^= (unsigned)((int)u >> 31) | 0x80000000u;   // monotone map
                g_usk[node * 4 + (j - 4)] = u;
            }
        }
        __syncwarp();
    }
}

// ---------------- GEMM: mma.sync bf16 3-term split + ldmatrix --------------
#define KP 40

__device__ __forceinline__ void hmma(float* c, const uint32_t* a,
                                     uint32_t b0, uint32_t b1) {
    asm volatile(
        "mma.sync.aligned.m16n8k16.row.col.f32.bf16.bf16.f32 "
        "{%0,%1,%2,%3}, {%4,%5,%6,%7}, {%8,%9}, {%0,%1,%2,%3};"
        : "+f"(c[0]), "+f"(c[1]), "+f"(c[2]), "+f"(c[3])
        : "r"(a[0]), "r"(a[1]), "r"(a[2]), "r"(a[3]), "r"(b0), "r"(b1));
}

#define LDSM4(R, addr) \
    asm volatile("ldmatrix.sync.aligned.m8n8.x4.shared.b16 {%0,%1,%2,%3}, [%4];" \
        : "=r"((R)[0]), "=r"((R)[1]), "=r"((R)[2]), "=r"((R)[3]) : "r"(addr))

__global__ void __launch_bounds__(256, 2)
k_gemm(const float* __restrict__ x) {
    __shared__ __nv_bfloat16 sAh[128][KP];
    __shared__ __nv_bfloat16 sAl[128][KP];
    __shared__ __nv_bfloat16 sBh[128][KP];
    __shared__ __nv_bfloat16 sBl[128][KP];

    int tid = threadIdx.x;
    int wid = tid >> 5, lane = tid & 31;
    int m0 = blockIdx.x * 128;
    int rb = (wid & 3) * 32;
    int nb = (wid >> 2) * 64;

    float acc[2][8][4];
    #pragma unroll
    for (int mt = 0; mt < 2; mt++)
        #pragma unroll
        for (int nt = 0; nt < 8; nt++)
            #pragma unroll
            for (int q = 0; q < 4; q++) acc[mt][nt][q] = 0.f;

    int tsub = lane >> 3;
    int trow = lane & 7;

    for (int st = 0; st < 4; st++) {
        int k0 = st * 32;
        #pragma unroll
        for (int it = 0; it < 2; it++) {
            int idx = tid + it * 256;
            int row = idx >> 2;
            int c0 = (idx & 3) * 8;
            int rr = m0 + row;
            float4 v0 = make_float4(0.f, 0.f, 0.f, 0.f), v1 = v0;
            if (rr < N_NODES) {
                v0 = *(const float4*)&x[rr * 128 + k0 + c0];
                v1 = *(const float4*)&x[rr * 128 + k0 + c0 + 4];
            }
            float vs[8] = {v0.x, v0.y, v0.z, v0.w, v1.x, v1.y, v1.z, v1.w};
            uint32_t hw[4], lw[4];
            #pragma unroll
            for (int q = 0; q < 4; q++) {
                __nv_bfloat16 h0 = __float2bfloat16(vs[2 * q]);
                __nv_bfloat16 h1 = __float2bfloat16(vs[2 * q + 1]);
                float l0 = vs[2 * q] - __bfloat162float(h0);
                float l1 = vs[2 * q + 1] - __bfloat162float(h1);
                hw[q] = (uint32_t)__bfloat16_as_ushort(h0) |
                        ((uint32_t)__bfloat16_as_ushort(h1) << 16);
                lw[q] = (uint32_t)__bfloat16_as_ushort(__float2bfloat16(l0)) |
                        ((uint32_t)__bfloat16_as_ushort(__float2bfloat16(l1)) << 16);
            }
            *(uint4*)&sAh[row][c0] = make_uint4(hw[0], hw[1], hw[2], hw[3]);
            *(uint4*)&sAl[row][c0] = make_uint4(lw[0], lw[1], lw[2], lw[3]);
            *(uint4*)&sBh[row][c0] = *(const uint4*)&g_wth[row * 128 + k0 + c0];
            *(uint4*)&sBl[row][c0] = *(const uint4*)&g_wtl[row * 128 + k0 + c0];
        }
        __syncthreads();

        #pragma unroll
        for (int ks = 0; ks < 2; ks++) {
            int ck = ks * 16;
            uint32_t Ah[2][4], Al[2][4];
            #pragma unroll
            for (int mt = 0; mt < 2; mt++) {
                int r = rb + mt * 16 + ((tsub & 1) << 3) + trow;
                int c = ck + ((tsub >> 1) << 3);
                LDSM4(Ah[mt], (uint32_t)__cvta_generic_to_shared(&sAh[r][c]));
                LDSM4(Al[mt], (uint32_t)__cvta_generic_to_shared(&sAl[r][c]));
            }
            #pragma unroll
            for (int np = 0; np < 4; np++) {
                int n = nb + np * 16 + ((tsub >> 1) << 3) + trow;
                int c = ck + ((tsub & 1) << 3);
                uint32_t Bh[4], Bl[4];
                LDSM4(Bh, (uint32_t)__cvta_generic_to_shared(&sBh[n][c]));
                LDSM4(Bl, (uint32_t)__cvta_generic_to_shared(&sBl[n][c]));
                #pragma unroll
                for (int mt = 0; mt < 2; mt++) {
                    hmma(acc[mt][2 * np],     Ah[mt], Bh[0], Bh[1]);
                    hmma(acc[mt][2 * np],     Ah[mt], Bl[0], Bl[1]);
                    hmma(acc[mt][2 * np],     Al[mt], Bh[0], Bh[1]);
                    hmma(acc[mt][2 * np + 1], Ah[mt], Bh[2], Bh[3]);
                    hmma(acc[mt][2 * np + 1], Ah[mt], Bl[2], Bl[3]);
                    hmma(acc[mt][2 * np + 1], Al[mt], Bh[2], Bh[3]);
                }
            }
        }
        __syncthreads();
    }

    #pragma unroll
    for (int mt = 0; mt < 2; mt++) {
        int r0 = m0 + rb + mt * 16 + (lane >> 2);
        #pragma unroll
        for (int nt = 0; nt < 8; nt++) {
            int col = nb + nt * 8 + (lane & 3) * 2;
            if (r0 < N_NODES)
                *(float2*)&g_h[r0 * 128 + col] =
                    make_float2(acc[mt][nt][0], acc[mt][nt][1]);
            if (r0 + 8 < N_NODES)
                *(float2*)&g_h[(r0 + 8) * 128 + col] =
                    make_float2(acc[mt][nt][2], acc[mt][nt][3]);
        }
    }
}

// ---------------- fused top-k + softmax + aggregate + ELU (round-10) -------
#define CSWAP(a, b) { ull _x = key[a], _y = key[b]; \
                      key[a] = (_x > _y) ? _x : _y; key[b] = (_x > _y) ? _y : _x; }
#define BUBBLE() { CSWAP(6,7) CSWAP(5,6) CSWAP(4,5) CSWAP(3,4) \
                   CSWAP(2,3) CSWAP(1,2) CSWAP(0,1) }

__global__ void __launch_bounds__(256) k_topkagg(float* __restrict__ out) {
    __shared__ float salpha[256][TOPK];
    __shared__ int   scol[256][TOPK];

    int tid = threadIdx.x;
    int gw0 = blockIdx.x * 256;

    // ---- phase 1: thread per (node,head)
    {
        int gw = gw0 + tid;
        if (gw < NPAIRS) {
            int node = gw >> 2;
            int head = gw & 3;
            int start = g_off[node];
            int end   = g_off[node + 1];
            int deg = end - start;

            ull key[8];
            #pragma unroll
            for (int r = 0; r < 8; r++) {
                ull kv = 0ull;
                if (r < deg) {
                    int c = g_col[start + r];
                    uint32_t u = g_usk[c * 4 + head];
                    kv = ((ull)u << 32) | (unsigned)c;
                }
                key[r] = kv;
            }
            CSWAP(0,1) CSWAP(2,3) CSWAP(4,5) CSWAP(6,7)
            CSWAP(0,2) CSWAP(1,3) CSWAP(4,6) CSWAP(5,7)
            CSWAP(1,2) CSWAP(5,6)
            CSWAP(0,4) CSWAP(1,5) CSWAP(2,6) CSWAP(3,7)
            CSWAP(2,4) CSWAP(3,5)
            CSWAP(1,2) CSWAP(3,4) CSWAP(5,6)

            int i = start + 8;
            for (; i + 1 < end; i += 2) {
                int c0 = g_col[i], c1 = g_col[i + 1];
                uint32_t u0 = g_usk[c0 * 4 + head];
                uint32_t u1 = g_usk[c1 * 4 + head];
                ull k0 = ((ull)u0 << 32) | (unsigned)c0;
                ull k1 = ((ull)u1 << 32) | (unsigned)c1;
                if (k0 > key[7]) { key[7] = k0; BUBBLE() }
                if (k1 > key[7]) { key[7] = k1; BUBBLE() }
            }
            if (i < end) {
                int c = g_col[i];
                uint32_t u = g_usk[c * 4 + head];
                ull kv = ((ull)u << 32) | (unsigned)c;
                if (kv > key[7]) { key[7] = kv; BUBBLE() }
            }

            int k = min(deg, TOPK);
            float si = g_si[gw];
            float sc[TOPK];
            #pragma unroll
            for (int r = 0; r < TOPK; r++) {
                unsigned u = (unsigned)(key[r] >> 32);
                u ^= (~((unsigned)((int)u >> 31))) | 0x80000000u;  // inverse map
                float s = si + __uint_as_float(u);
                sc[r] = (s > 0.f) ? s : 0.2f * s;                  // leaky
            }
            float maxe = sc[0];
            float p[TOPK];
            float sum = 0.f;
            #pragma unroll
            for (int r = 0; r < TOPK; r++) {
                float e = (r < k) ? __expf(sc[r] - maxe) : 0.f;
                p[r] = e;
                sum += e;
            }
            float inv = 1.f / sum;
            #pragma unroll
            for (int r = 0; r < TOPK; r++) {
                salpha[tid][r] = p[r] * inv;
                scol[tid][r]   = (int)(unsigned)(key[r] & 0xffffffffull);
            }
        } else {
            #pragma unroll
            for (int r = 0; r < TOPK; r++) { salpha[tid][r] = 0.f; scol[tid][r] = 0; }
        }
    }
    __syncthreads();

    // ---- phase 2: warp per pair
    int wid = tid >> 5, lane = tid & 31;
    for (int p = 0; p < 32; p++) {
        int lp = wid * 32 + p;
        int gw = gw0 + lp;
        if (gw >= NPAIRS) break;
        int node = gw >> 2;
        int head = gw & 3;
        float acc = 0.f;
        #pragma unroll
        for (int r = 0; r < TOPK; r++) {
            float a = salpha[lp][r];
            int   c = scol[lp][r];
            acc += a * __ldg(&g_h[c * 128 + head * OUT_CH + lane]);
        }
        out[node * 128 + head * OUT_CH + lane] = (acc > 0.f) ? acc : expm1f(acc);
    }
}

// ---------------- launch (slot 3 = k_scores for ncu) ------------------------
extern "C" void kernel_launch(void* const* d_in, const int* in_sizes, int n_in,
                              void* d_out, int out_size) {
    const float* x   = (const float*)d_in[0];
    const float* W   = (const float*)d_in[1];
    const float* att = (const float*)d_in[2];
    const int*   ei  = (const int*)d_in[3];
    float* out = (float*)d_out;

    k_prep<<<64, 256>>>(W, att);                                    // 0
    k_hist<<<(N_EDGES / 4 + 255) / 256, 256>>>(ei);                 // 1
    k_scan1<<<NB_SCAN, 1024>>>();                                   // 2
    k_scores<<<(N_NODES + 63) / 64, 256>>>(x);                      // 3 (profiled)
    k_gemm<<<(N_NODES + 127) / 128, 256>>>(x);                      // 4
    k_scan3<<<NB_SCAN, 1024>>>();                                   // 5
    k_scatter<<<(ET + 255) / 256, 256>>>(ei);                       // 6
    k_topkagg<<<(NPAIRS + 255) / 256, 256>>>(out);                  // 7
}

// round 14
// speedup vs baseline: 1.4316x; 1.0526x over previous
#include <cuda_runtime.h>
#include <cuda_bf16.h>
#include <math.h>
#include <stdint.h>

#define N_NODES 50000
#define N_EDGES 800000
#define ET (N_EDGES + N_NODES)
#define HEADS 4
#define OUT_CH 32
#define TOPK 8
#define NPAIRS (N_NODES * HEADS)
#define NB_SCAN ((N_NODES + 1023) / 1024)
typedef unsigned long long ull;

#define GEMM_BLOCKS   ((N_NODES + 127) / 128)          // 391
#define SCORES_BLOCKS ((N_NODES + 63) / 64)            // 782
#define SCAT_BLOCKS   ((ET + 255) / 256)               // 3321
#define HIST_BLOCKS   ((N_EDGES / 4 + 255) / 256)      // 782

// ---------------- scratch ----------------
__device__ __align__(16) float g_h[N_NODES * 128];           // 25.6 MB
__device__ __align__(16) float g_si[NPAIRS];
__device__ __align__(16) uint32_t g_usk[NPAIRS];             // monotone(sj) keys
__device__ int   g_deg[N_NODES + 1];     // .bss zero; reset by scan1 each run
__device__ int   g_off[N_NODES + 1];
__device__ int   g_cur[N_NODES];
__device__ int   g_col[ET];
__device__ int   g_bsum[NB_SCAN + 1];
__device__ __align__(16) __nv_bfloat16 g_wth[128 * 128];     // W^T hi [n][k]
__device__ __align__(16) __nv_bfloat16 g_wtl[128 * 128];     // W^T lo [n][k]
__device__ __align__(16) float g_a2[128 * 8];                // W @ att combos

// ---------------- fused hist + prep ----------------
__global__ void k_histprep(const int* __restrict__ ei,
                           const float* __restrict__ W,
                           const float* __restrict__ att) {
    int b = blockIdx.x;
    int tid = threadIdx.x;
    if (b < HIST_BLOCKS) {
        int e = (b * 256 + tid) * 4;
        if (e < N_EDGES) {
            int4 v = *(const int4*)&ei[e];
            atomicAdd(&g_deg[v.x], 1);
            atomicAdd(&g_deg[v.y], 1);
            atomicAdd(&g_deg[v.z], 1);
            atomicAdd(&g_deg[v.w], 1);
        }
    } else {
        int t = (b - HIST_BLOCKS) * 256 + tid;
        if (t < 16384) {
            int n = t >> 7, k = t & 127;
            float w = W[k * 128 + n];
            __nv_bfloat16 hi = __float2bfloat16(w);
            float lo = w - __bfloat162float(hi);
            g_wth[n * 128 + k] = hi;
            g_wtl[n * 128 + k] = __float2bfloat16(lo);
        }
        if (t < 1024) {
            int k = t >> 3, j = t & 7;
            int h = j & 3, part = j >> 2;
            float s = 0.f;
            #pragma unroll
            for (int c = 0; c < 32; c++)
                s += W[k * 128 + h * 32 + c] * att[h * 64 + part * 32 + c];
            g_a2[k * 8 + j] = s;
        }
    }
}

// ---------------- scans ----------------
__global__ void k_scan1() {
    __shared__ int wsum[32];
    int tid = threadIdx.x;
    int lane = tid & 31, w = tid >> 5;
    int i = blockIdx.x * 1024 + tid;
    int v = 0;
    if (i < N_NODES) {
        v = g_deg[i] + 1;       // +1 self-loop
        g_deg[i] = 0;           // reset for next graph replay
        g_cur[i] = 0;
    }
    int s = v;
    #pragma unroll
    for (int o = 1; o < 32; o <<= 1) {
        int t = __shfl_up_sync(0xffffffffu, s, o);
        if (lane >= o) s += t;
    }
    if (lane == 31) wsum[w] = s;
    __syncthreads();
    if (w == 0) {
        int t = wsum[lane];
        #pragma unroll
        for (int o = 1; o < 32; o <<= 1) {
            int u = __shfl_up_sync(0xffffffffu, t, o);
            if (lane >= o) t += u;
        }
        wsum[lane] = t;
        if (lane == 31) g_bsum[blockIdx.x] = t;
    }
    __syncthreads();
    int carry = (w > 0) ? wsum[w - 1] : 0;
    if (i < N_NODES) g_off[i] = s - v + carry;
}

__global__ void k_scan3() {
    __shared__ int carry;
    int tid = threadIdx.x;
    if (tid < 32) {
        int s = 0;
        for (int b = tid; b < blockIdx.x; b += 32) s += g_bsum[b];
        #pragma unroll
        for (int o = 16; o; o >>= 1) s += __shfl_xor_sync(0xffffffffu, s, o);
        if (tid == 0) carry = s;
    }
    __syncthreads();
    int i = blockIdx.x * 1024 + tid;
    if (i < N_NODES) g_off[i] += carry;
    if (i == 0) g_off[N_NODES] = ET;
}

// ---------------- fused gemm | scores | scatter ----------------
#define KP 40

__device__ __forceinline__ void hmma(float* c, const uint32_t* a,
                                     uint32_t b0, uint32_t b1) {
    asm volatile(
        "mma.sync.aligned.m16n8k16.row.col.f32.bf16.bf16.f32 "
        "{%0,%1,%2,%3}, {%4,%5,%6,%7}, {%8,%9}, {%0,%1,%2,%3};"
        : "+f"(c[0]), "+f"(c[1]), "+f"(c[2]), "+f"(c[3])
        : "r"(a[0]), "r"(a[1]), "r"(a[2]), "r"(a[3]), "r"(b0), "r"(b1));
}

#define LDSM4(R, addr) \
    asm volatile("ldmatrix.sync.aligned.m8n8.x4.shared.b16 {%0,%1,%2,%3}, [%4];" \
        : "=r"((R)[0]), "=r"((R)[1]), "=r"((R)[2]), "=r"((R)[3]) : "r"(addr))

__device__ void gemm_body(int bs, const float* __restrict__ x, char* sb) {
    __nv_bfloat16 (*sAh)[KP] = (__nv_bfloat16(*)[KP])(sb);
    __nv_bfloat16 (*sAl)[KP] = (__nv_bfloat16(*)[KP])(sb + 10240);
    __nv_bfloat16 (*sBh)[KP] = (__nv_bfloat16(*)[KP])(sb + 20480);
    __nv_bfloat16 (*sBl)[KP] = (__nv_bfloat16(*)[KP])(sb + 30720);

    int tid = threadIdx.x;
    int wid = tid >> 5, lane = tid & 31;
    int m0 = bs * 128;
    int rb = (wid & 3) * 32;
    int nb = (wid >> 2) * 64;

    float acc[2][8][4];
    #pragma unroll
    for (int mt = 0; mt < 2; mt++)
        #pragma unroll
        for (int nt = 0; nt < 8; nt++)
            #pragma unroll
            for (int q = 0; q < 4; q++) acc[mt][nt][q] = 0.f;

    int tsub = lane >> 3;
    int trow = lane & 7;

    for (int st = 0; st < 4; st++) {
        int k0 = st * 32;
        #pragma unroll
        for (int it = 0; it < 2; it++) {
            int idx = tid + it * 256;
            int row = idx >> 2;
            int c0 = (idx & 3) * 8;
            int rr = m0 + row;
            float4 v0 = make_float4(0.f, 0.f, 0.f, 0.f), v1 = v0;
            if (rr < N_NODES) {
                v0 = *(const float4*)&x[rr * 128 + k0 + c0];
                v1 = *(const float4*)&x[rr * 128 + k0 + c0 + 4];
            }
            float vs[8] = {v0.x, v0.y, v0.z, v0.w, v1.x, v1.y, v1.z, v1.w};
            uint32_t hw[4], lw[4];
            #pragma unroll
            for (int q = 0; q < 4; q++) {
                __nv_bfloat16 h0 = __float2bfloat16(vs[2 * q]);
                __nv_bfloat16 h1 = __float2bfloat16(vs[2 * q + 1]);
                float l0 = vs[2 * q] - __bfloat162float(h0);
                float l1 = vs[2 * q + 1] - __bfloat162float(h1);
                hw[q] = (uint32_t)__bfloat16_as_ushort(h0) |
                        ((uint32_t)__bfloat16_as_ushort(h1) << 16);
                lw[q] = (uint32_t)__bfloat16_as_ushort(__float2bfloat16(l0)) |
                        ((uint32_t)__bfloat16_as_ushort(__float2bfloat16(l1)) << 16);
            }
            *(uint4*)&sAh[row][c0] = make_uint4(hw[0], hw[1], hw[2], hw[3]);
            *(uint4*)&sAl[row][c0] = make_uint4(lw[0], lw[1], lw[2], lw[3]);
            *(uint4*)&sBh[row][c0] = *(const uint4*)&g_wth[row * 128 + k0 + c0];
            *(uint4*)&sBl[row][c0] = *(const uint4*)&g_wtl[row * 128 + k0 + c0];
        }
        __syncthreads();

        #pragma unroll
        for (int ks = 0; ks < 2; ks++) {
            int ck = ks * 16;
            uint32_t Ah[2][4], Al[2][4];
            #pragma unroll
            for (int mt = 0; mt < 2; mt++) {
                int r = rb + mt * 16 + ((tsub & 1) << 3) + trow;
                int c = ck + ((tsub >> 1) << 3);
                LDSM4(Ah[mt], (uint32_t)__cvta_generic_to_shared(&sAh[r][c]));
                LDSM4(Al[mt], (uint32_t)__cvta_generic_to_shared(&sAl[r][c]));
            }
            #pragma unroll
            for (int np = 0; np < 4; np++) {
                int n = nb + np * 16 + ((tsub >> 1) << 3) + trow;
                int c = ck + ((tsub & 1) << 3);
                uint32_t Bh[4], Bl[4];
                LDSM4(Bh, (uint32_t)__cvta_generic_to_shared(&sBh[n][c]));
                LDSM4(Bl, (uint32_t)__cvta_generic_to_shared(&sBl[n][c]));
                #pragma unroll
                for (int mt = 0; mt < 2; mt++) {
                    hmma(acc[mt][2 * np],     Ah[mt], Bh[0], Bh[1]);
                    hmma(acc[mt][2 * np],     Ah[mt], Bl[0], Bl[1]);
                    hmma(acc[mt][2 * np],     Al[mt], Bh[0], Bh[1]);
                    hmma(acc[mt][2 * np + 1], Ah[mt], Bh[2], Bh[3]);
                    hmma(acc[mt][2 * np + 1], Ah[mt], Bl[2], Bl[3]);
                    hmma(acc[mt][2 * np + 1], Al[mt], Bh[2], Bh[3]);
                }
            }
        }
        __syncthreads();
    }

    #pragma unroll
    for (int mt = 0; mt < 2; mt++) {
        int r0 = m0 + rb + mt * 16 + (lane >> 2);
        #pragma unroll
        for (int nt = 0; nt < 8; nt++) {
            int col = nb + nt * 8 + (lane & 3) * 2;
            if (r0 < N_NODES)
                *(float2*)&g_h[r0 * 128 + col] =
                    make_float2(acc[mt][nt][0], acc[mt][nt][1]);
            if (r0 + 8 < N_NODES)
                *(float2*)&g_h[(r0 + 8) * 128 + col] =
                    make_float2(acc[mt][nt][2], acc[mt][nt][3]);
        }
    }
}

__device__ void scores_body(int bs, const float* __restrict__ x, char* sb) {
    float (*srow)[132] = (float(*)[132])sb;
    int tid = threadIdx.x;
    int w = tid >> 5, lane = tid & 31;
    int j = lane >> 2, rot = lane & 3;

    float4 areg[8];
    #pragma unroll
    for (int i = 0; i < 8; i++) {
        int kb = rot * 32 + ((i + 2 * rot) & 7) * 4;
        areg[i].x = g_a2[(kb + 0) * 8 + j];
        areg[i].y = g_a2[(kb + 1) * 8 + j];
        areg[i].z = g_a2[(kb + 2) * 8 + j];
        areg[i].w = g_a2[(kb + 3) * 8 + j];
    }

    int base = (bs * 8 + w) * 8;

    float4 xv[8];
    #pragma unroll
    for (int n = 0; n < 8; n++) {
        int node = base + n;
        xv[n] = (node < N_NODES) ? *(const float4*)&x[node * 128 + lane * 4]
                                 : make_float4(0.f, 0.f, 0.f, 0.f);
    }

    #pragma unroll
    for (int n = 0; n < 8; n++) {
        int node = base + n;
        if (node >= N_NODES) break;
        *(float4*)&srow[w][lane * 4] = xv[n];
        __syncwarp();
        float acc = 0.f;
        #pragma unroll
        for (int i = 0; i < 8; i++) {
            const float4 v = *(const float4*)&srow[w][rot * 32 + ((i + 2 * rot) & 7) * 4];
            acc += v.x * areg[i].x + v.y * areg[i].y + v.z * areg[i].z + v.w * areg[i].w;
        }
        acc += __shfl_xor_sync(0xffffffffu, acc, 1);
        acc += __shfl_xor_sync(0xffffffffu, acc, 2);
        if (rot == 0) {
            if (j < 4) {
                g_si[node * 4 + j] = acc;
            } else {
                unsigned u = __float_as_uint(acc);
                u ^= (unsigned)((int)u >> 31) | 0x80000000u;   // monotone map
                g_usk[node * 4 + (j - 4)] = u;
            }
        }
        __syncwarp();
    }
}

__device__ void scatter_body(int bs, const int* __restrict__ ei) {
    int idx = bs * 256 + threadIdx.x;
    if (idx >= ET) return;
    int r, c;
    if (idx < N_EDGES) { r = ei[idx]; c = ei[N_EDGES + idx]; }
    else               { r = idx - N_EDGES; c = r; }
    int p = g_off[r] + atomicAdd(&g_cur[r], 1);
    g_col[p] = c;
}

__global__ void __launch_bounds__(256)
k_fused(const float* __restrict__ x, const int* __restrict__ ei) {
    __shared__ __align__(16) char sbuf[40960];
    int b = blockIdx.x;
    if (b < GEMM_BLOCKS)                      gemm_body(b, x, sbuf);
    else if (b < GEMM_BLOCKS + SCORES_BLOCKS) scores_body(b - GEMM_BLOCKS, x, sbuf);
    else                                      scatter_body(b - GEMM_BLOCKS - SCORES_BLOCKS, ei);
}

// ---------------- fused top-k + softmax + aggregate + ELU ------------------
#define CSWAP(a, b) { ull _x = key[a], _y = key[b]; \
                      key[a] = (_x > _y) ? _x : _y; key[b] = (_x > _y) ? _y : _x; }
#define BUBBLE() { CSWAP(6,7) CSWAP(5,6) CSWAP(4,5) CSWAP(3,4) \
                   CSWAP(2,3) CSWAP(1,2) CSWAP(0,1) }

__global__ void __launch_bounds__(256) k_topkagg(float* __restrict__ out) {
    __shared__ float salpha[256][TOPK];
    __shared__ int   scol[256][TOPK];

    int tid = threadIdx.x;
    int gw0 = blockIdx.x * 256;

    // ---- phase 1: thread per (node,head)
    {
        int gw = gw0 + tid;
        if (gw < NPAIRS) {
            int node = gw >> 2;
            int head = gw & 3;
            int start = g_off[node];
            int end   = g_off[node + 1];
            int deg = end - start;

            ull key[8];
            #pragma unroll
            for (int r = 0; r < 8; r++) {
                ull kv = 0ull;
                if (r < deg) {
                    int c = g_col[start + r];
                    uint32_t u = g_usk[c * 4 + head];
                    kv = ((ull)u << 32) | (unsigned)c;
                }
                key[r] = kv;
            }
            CSWAP(0,1) CSWAP(2,3) CSWAP(4,5) CSWAP(6,7)
            CSWAP(0,2) CSWAP(1,3) CSWAP(4,6) CSWAP(5,7)
            CSWAP(1,2) CSWAP(5,6)
            CSWAP(0,4) CSWAP(1,5) CSWAP(2,6) CSWAP(3,7)
            CSWAP(2,4) CSWAP(3,5)
            CSWAP(1,2) CSWAP(3,4) CSWAP(5,6)

            int i = start + 8;
            for (; i + 1 < end; i += 2) {
                int c0 = g_col[i], c1 = g_col[i + 1];
                uint32_t u0 = g_usk[c0 * 4 + head];
                uint32_t u1 = g_usk[c1 * 4 + head];
                ull k0 = ((ull)u0 << 32) | (unsigned)c0;
                ull k1 = ((ull)u1 << 32) | (unsigned)c1;
                if (k0 > key[7]) { key[7] = k0; BUBBLE() }
                if (k1 > key[7]) { key[7] = k1; BUBBLE() }
            }
            if (i < end) {
                int c = g_col[i];
                uint32_t u = g_usk[c * 4 + head];
                ull kv = ((ull)u << 32) | (unsigned)c;
                if (kv > key[7]) { key[7] = kv; BUBBLE() }
            }

            int k = min(deg, TOPK);
            float si = g_si[gw];
            float sc[TOPK];
            #pragma unroll
            for (int r = 0; r < TOPK; r++) {
                unsigned u = (unsigned)(key[r] >> 32);
                u ^= (~((unsigned)((int)u >> 31))) | 0x80000000u;  // inverse map
                float s = si + __uint_as_float(u);
                sc[r] = (s > 0.f) ? s : 0.2f * s;                  // leaky
            }
            float maxe = sc[0];
            float p[TOPK];
            float sum = 0.f;
            #pragma unroll
            for (int r = 0; r < TOPK; r++) {
                float e = (r < k) ? __expf(sc[r] - maxe) : 0.f;
                p[r] = e;
                sum += e;
            }
            float inv = 1.f / sum;
            #pragma unroll
            for (int r = 0; r < TOPK; r++) {
                salpha[tid][r] = p[r] * inv;
                scol[tid][r]   = (int)(unsigned)(key[r] & 0xffffffffull);
            }
        } else {
            #pragma unroll
            for (int r = 0; r < TOPK; r++) { salpha[tid][r] = 0.f; scol[tid][r] = 0; }
        }
    }
    __syncthreads();

    // ---- phase 2: warp per pair
    int wid = tid >> 5, lane = tid & 31;
    for (int p = 0; p < 32; p++) {
        int lp = wid * 32 + p;
        int gw = gw0 + lp;
        if (gw >= NPAIRS) break;
        int node = gw >> 2;
        int head = gw & 3;
        float acc = 0.f;
        #pragma unroll
        for (int r = 0; r < TOPK; r++) {
            float a = salpha[lp][r];
            int   c = scol[lp][r];
            acc += a * __ldg(&g_h[c * 128 + head * OUT_CH + lane]);
        }
        out[node * 128 + head * OUT_CH + lane] = (acc > 0.f) ? acc : expm1f(acc);
    }
}

// ---------------- launch: 5 launches, single stream -------------------------
extern "C" void kernel_launch(void* const* d_in, const int* in_sizes, int n_in,
                              void* d_out, int out_size) {
    const float* x   = (const float*)d_in[0];
    const float* W   = (const float*)d_in[1];
    const float* att = (const float*)d_in[2];
    const int*   ei  = (const int*)d_in[3];
    float* out = (float*)d_out;

    k_histprep<<<HIST_BLOCKS + 64, 256>>>(ei, W, att);                 // 0
    k_scan1<<<NB_SCAN, 1024>>>();                                      // 1
    k_scan3<<<NB_SCAN, 1024>>>();                                      // 2
    k_fused<<<GEMM_BLOCKS + SCORES_BLOCKS + SCAT_BLOCKS, 256>>>(x, ei);// 3 (profiled)
    k_topkagg<<<(NPAIRS + 255) / 256, 256>>>(out);                     // 4
}

// round 15
// speedup vs baseline: 1.4349x; 1.0023x over previous
#include <cuda_runtime.h>
#include <cuda_bf16.h>
#include <math.h>
#include <stdint.h>

#define N_NODES 50000
#define N_EDGES 800000
#define ET (N_EDGES + N_NODES)
#define HEADS 4
#define OUT_CH 32
#define TOPK 8
#define NPAIRS (N_NODES * HEADS)
#define NB_SCAN ((N_NODES + 1023) / 1024)
typedef unsigned long long ull;

#define GEMM_BLOCKS   ((N_NODES + 127) / 128)          // 391
#define SCORES_BLOCKS ((N_NODES + 63) / 64)            // 782
#define SCAT_BLOCKS   ((ET + 255) / 256)               // 3321
#define HIST_BLOCKS   ((N_EDGES / 4 + 255) / 256)      // 782

// ---------------- scratch ----------------
__device__ __align__(16) float g_h[N_NODES * 128];           // 25.6 MB
__device__ __align__(16) float g_si[NPAIRS];
__device__ __align__(16) uint32_t g_usk[NPAIRS];             // monotone(sj) keys
__device__ int   g_deg[N_NODES + 1];     // .bss zero; reset by scan1 each run
__device__ int   g_off[N_NODES + 1];
__device__ int   g_cur[N_NODES];
__device__ int   g_col[ET];
__device__ int   g_bsum[NB_SCAN + 1];
__device__ __align__(16) __nv_bfloat16 g_wth[128 * 128];     // W^T hi [n][k]
__device__ __align__(16) __nv_bfloat16 g_wtl[128 * 128];     // W^T lo [n][k]
__device__ __align__(16) float g_a2[128 * 8];                // W @ att combos

// ---------------- fused hist + prep ----------------
__global__ void k_histprep(const int* __restrict__ ei,
                           const float* __restrict__ W,
                           const float* __restrict__ att) {
    int b = blockIdx.x;
    int tid = threadIdx.x;
    if (b < HIST_BLOCKS) {
        int e = (b * 256 + tid) * 4;
        if (e < N_EDGES) {
            int4 v = *(const int4*)&ei[e];
            atomicAdd(&g_deg[v.x], 1);
            atomicAdd(&g_deg[v.y], 1);
            atomicAdd(&g_deg[v.z], 1);
            atomicAdd(&g_deg[v.w], 1);
        }
    } else {
        int t = (b - HIST_BLOCKS) * 256 + tid;
        if (t < 16384) {
            int n = t >> 7, k = t & 127;
            float w = W[k * 128 + n];
            __nv_bfloat16 hi = __float2bfloat16(w);
            float lo = w - __bfloat162float(hi);
            g_wth[n * 128 + k] = hi;
            g_wtl[n * 128 + k] = __float2bfloat16(lo);
        }
        if (t < 1024) {
            int k = t >> 3, j = t & 7;
            int h = j & 3, part = j >> 2;
            float s = 0.f;
            #pragma unroll
            for (int c = 0; c < 32; c++)
                s += W[k * 128 + h * 32 + c] * att[h * 64 + part * 32 + c];
            g_a2[k * 8 + j] = s;
        }
    }
}

// ---------------- scans ----------------
__global__ void k_scan1() {
    __shared__ int wsum[32];
    int tid = threadIdx.x;
    int lane = tid & 31, w = tid >> 5;
    int i = blockIdx.x * 1024 + tid;
    int v = 0;
    if (i < N_NODES) {
        v = g_deg[i] + 1;       // +1 self-loop
        g_deg[i] = 0;           // reset for next graph replay
        g_cur[i] = 0;
    }
    int s = v;
    #pragma unroll
    for (int o = 1; o < 32; o <<= 1) {
        int t = __shfl_up_sync(0xffffffffu, s, o);
        if (lane >= o) s += t;
    }
    if (lane == 31) wsum[w] = s;
    __syncthreads();
    if (w == 0) {
        int t = wsum[lane];
        #pragma unroll
        for (int o = 1; o < 32; o <<= 1) {
            int u = __shfl_up_sync(0xffffffffu, t, o);
            if (lane >= o) t += u;
        }
        wsum[lane] = t;
        if (lane == 31) g_bsum[blockIdx.x] = t;
    }
    __syncthreads();
    int carry = (w > 0) ? wsum[w - 1] : 0;
    if (i < N_NODES) g_off[i] = s - v + carry;
}

__global__ void k_scan3() {
    __shared__ int carry;
    int tid = threadIdx.x;
    if (tid < 32) {
        int s = 0;
        for (int b = tid; b < blockIdx.x; b += 32) s += g_bsum[b];
        #pragma unroll
        for (int o = 16; o; o >>= 1) s += __shfl_xor_sync(0xffffffffu, s, o);
        if (tid == 0) carry = s;
    }
    __syncthreads();
    int i = blockIdx.x * 1024 + tid;
    if (i < N_NODES) g_off[i] += carry;
    if (i == 0) g_off[N_NODES] = ET;
}

// ---------------- fused gemm | scores | scatter ----------------
#define KP 40

__device__ __forceinline__ void hmma(float* c, const uint32_t* a,
                                     uint32_t b0, uint32_t b1) {
    asm volatile(
        "mma.sync.aligned.m16n8k16.row.col.f32.bf16.bf16.f32 "
        "{%0,%1,%2,%3}, {%4,%5,%6,%7}, {%8,%9}, {%0,%1,%2,%3};"
        : "+f"(c[0]), "+f"(c[1]), "+f"(c[2]), "+f"(c[3])
        : "r"(a[0]), "r"(a[1]), "r"(a[2]), "r"(a[3]), "r"(b0), "r"(b1));
}

#define LDSM4(R, addr) \
    asm volatile("ldmatrix.sync.aligned.m8n8.x4.shared.b16 {%0,%1,%2,%3}, [%4];" \
        : "=r"((R)[0]), "=r"((R)[1]), "=r"((R)[2]), "=r"((R)[3]) : "r"(addr))

__device__ void gemm_body(int bs, const float* __restrict__ x, char* sb) {
    __nv_bfloat16 (*sAh)[KP] = (__nv_bfloat16(*)[KP])(sb);
    __nv_bfloat16 (*sAl)[KP] = (__nv_bfloat16(*)[KP])(sb + 10240);
    __nv_bfloat16 (*sBh)[KP] = (__nv_bfloat16(*)[KP])(sb + 20480);
    __nv_bfloat16 (*sBl)[KP] = (__nv_bfloat16(*)[KP])(sb + 30720);

    int tid = threadIdx.x;
    int wid = tid >> 5, lane = tid & 31;
    int m0 = bs * 128;
    int rb = (wid & 3) * 32;
    int nb = (wid >> 2) * 64;

    float acc[2][8][4];
    #pragma unroll
    for (int mt = 0; mt < 2; mt++)
        #pragma unroll
        for (int nt = 0; nt < 8; nt++)
            #pragma unroll
            for (int q = 0; q < 4; q++) acc[mt][nt][q] = 0.f;

    int tsub = lane >> 3;
    int trow = lane & 7;

    for (int st = 0; st < 4; st++) {
        int k0 = st * 32;
        #pragma unroll
        for (int it = 0; it < 2; it++) {
            int idx = tid + it * 256;
            int row = idx >> 2;
            int c0 = (idx & 3) * 8;
            int rr = m0 + row;
            float4 v0 = make_float4(0.f, 0.f, 0.f, 0.f), v1 = v0;
            if (rr < N_NODES) {
                v0 = *(const float4*)&x[rr * 128 + k0 + c0];
                v1 = *(const float4*)&x[rr * 128 + k0 + c0 + 4];
            }
            float vs[8] = {v0.x, v0.y, v0.z, v0.w, v1.x, v1.y, v1.z, v1.w};
            uint32_t hw[4], lw[4];
            #pragma unroll
            for (int q = 0; q < 4; q++) {
                __nv_bfloat16 h0 = __float2bfloat16(vs[2 * q]);
                __nv_bfloat16 h1 = __float2bfloat16(vs[2 * q + 1]);
                float l0 = vs[2 * q] - __bfloat162float(h0);
                float l1 = vs[2 * q + 1] - __bfloat162float(h1);
                hw[q] = (uint32_t)__bfloat16_as_ushort(h0) |
                        ((uint32_t)__bfloat16_as_ushort(h1) << 16);
                lw[q] = (uint32_t)__bfloat16_as_ushort(__float2bfloat16(l0)) |
                        ((uint32_t)__bfloat16_as_ushort(__float2bfloat16(l1)) << 16);
            }
            *(uint4*)&sAh[row][c0] = make_uint4(hw[0], hw[1], hw[2], hw[3]);
            *(uint4*)&sAl[row][c0] = make_uint4(lw[0], lw[1], lw[2], lw[3]);
            *(uint4*)&sBh[row][c0] = *(const uint4*)&g_wth[row * 128 + k0 + c0];
            *(uint4*)&sBl[row][c0] = *(const uint4*)&g_wtl[row * 128 + k0 + c0];
        }
        __syncthreads();

        #pragma unroll
        for (int ks = 0; ks < 2; ks++) {
            int ck = ks * 16;
            uint32_t Ah[2][4], Al[2][4];
            #pragma unroll
            for (int mt = 0; mt < 2; mt++) {
                int r = rb + mt * 16 + ((tsub & 1) << 3) + trow;
                int c = ck + ((tsub >> 1) << 3);
                LDSM4(Ah[mt], (uint32_t)__cvta_generic_to_shared(&sAh[r][c]));
                LDSM4(Al[mt], (uint32_t)__cvta_generic_to_shared(&sAl[r][c]));
            }
            #pragma unroll
            for (int np = 0; np < 4; np++) {
                int n = nb + np * 16 + ((tsub >> 1) << 3) + trow;
                int c = ck + ((tsub & 1) << 3);
                uint32_t Bh[4], Bl[4];
                LDSM4(Bh, (uint32_t)__cvta_generic_to_shared(&sBh[n][c]));
                LDSM4(Bl, (uint32_t)__cvta_generic_to_shared(&sBl[n][c]));
                #pragma unroll
                for (int mt = 0; mt < 2; mt++) {
                    hmma(acc[mt][2 * np],     Ah[mt], Bh[0], Bh[1]);
                    hmma(acc[mt][2 * np],     Ah[mt], Bl[0], Bl[1]);
                    hmma(acc[mt][2 * np],     Al[mt], Bh[0], Bh[1]);
                    hmma(acc[mt][2 * np + 1], Ah[mt], Bh[2], Bh[3]);
                    hmma(acc[mt][2 * np + 1], Ah[mt], Bl[2], Bl[3]);
                    hmma(acc[mt][2 * np + 1], Al[mt], Bh[2], Bh[3]);
                }
            }
        }
        __syncthreads();
    }

    #pragma unroll
    for (int mt = 0; mt < 2; mt++) {
        int r0 = m0 + rb + mt * 16 + (lane >> 2);
        #pragma unroll
        for (int nt = 0; nt < 8; nt++) {
            int col = nb + nt * 8 + (lane & 3) * 2;
            if (r0 < N_NODES)
                *(float2*)&g_h[r0 * 128 + col] =
                    make_float2(acc[mt][nt][0], acc[mt][nt][1]);
            if (r0 + 8 < N_NODES)
                *(float2*)&g_h[(r0 + 8) * 128 + col] =
                    make_float2(acc[mt][nt][2], acc[mt][nt][3]);
        }
    }
}

__device__ void scores_body(int bs, const float* __restrict__ x, char* sb) {
    float (*srow)[132] = (float(*)[132])sb;
    int tid = threadIdx.x;
    int w = tid >> 5, lane = tid & 31;
    int j = lane >> 2, rot = lane & 3;

    float4 areg[8];
    #pragma unroll
    for (int i = 0; i < 8; i++) {
        int kb = rot * 32 + ((i + 2 * rot) & 7) * 4;
        areg[i].x = g_a2[(kb + 0) * 8 + j];
        areg[i].y = g_a2[(kb + 1) * 8 + j];
        areg[i].z = g_a2[(kb + 2) * 8 + j];
        areg[i].w = g_a2[(kb + 3) * 8 + j];
    }

    int base = (bs * 8 + w) * 8;

    float4 xv[8];
    #pragma unroll
    for (int n = 0; n < 8; n++) {
        int node = base + n;
        xv[n] = (node < N_NODES) ? *(const float4*)&x[node * 128 + lane * 4]
                                 : make_float4(0.f, 0.f, 0.f, 0.f);
    }

    #pragma unroll
    for (int n = 0; n < 8; n++) {
        int node = base + n;
        if (node >= N_NODES) break;
        *(float4*)&srow[w][lane * 4] = xv[n];
        __syncwarp();
        float acc = 0.f;
        #pragma unroll
        for (int i = 0; i < 8; i++) {
            const float4 v = *(const float4*)&srow[w][rot * 32 + ((i + 2 * rot) & 7) * 4];
            acc += v.x * areg[i].x + v.y * areg[i].y + v.z * areg[i].z + v.w * areg[i].w;
        }
        acc += __shfl_xor_sync(0xffffffffu, acc, 1);
        acc += __shfl_xor_sync(0xffffffffu, acc, 2);
        if (rot == 0) {
            if (j < 4) {
                g_si[node * 4 + j] = acc;
            } else {
                unsigned u = __float_as_uint(acc);
                u ^= (unsigned)((int)u >> 31) | 0x80000000u;   // monotone map
                g_usk[node * 4 + (j - 4)] = u;
            }
        }
        __syncwarp();
    }
}

__device__ void scatter_body(int bs, const int* __restrict__ ei) {
    int idx = bs * 256 + threadIdx.x;
    if (idx >= ET) return;
    int r, c;
    if (idx < N_EDGES) { r = ei[idx]; c = ei[N_EDGES + idx]; }
    else               { r = idx - N_EDGES; c = r; }
    int p = g_off[r] + atomicAdd(&g_cur[r], 1);
    g_col[p] = c;
}

__global__ void __launch_bounds__(256)
k_fused(const float* __restrict__ x, const int* __restrict__ ei) {
    __shared__ __align__(16) char sbuf[40960];
    int b = blockIdx.x;
    if (b < GEMM_BLOCKS)                      gemm_body(b, x, sbuf);
    else if (b < GEMM_BLOCKS + SCORES_BLOCKS) scores_body(b - GEMM_BLOCKS, x, sbuf);
    else                                      scatter_body(b - GEMM_BLOCKS - SCORES_BLOCKS, ei);
}

// ---------------- fused top-k + softmax + aggregate + ELU ------------------
#define CSWAP(a, b) { ull _x = key[a], _y = key[b]; \
                      key[a] = (_x > _y) ? _x : _y; key[b] = (_x > _y) ? _y : _x; }
#define BUBBLE() { CSWAP(6,7) CSWAP(5,6) CSWAP(4,5) CSWAP(3,4) \
                   CSWAP(2,3) CSWAP(1,2) CSWAP(0,1) }

__global__ void __launch_bounds__(256) k_topkagg(float* __restrict__ out) {
    __shared__ float salpha[256][TOPK];
    __shared__ int   scol[256][TOPK];

    int tid = threadIdx.x;
    int gw0 = blockIdx.x * 256;

    // ---- phase 1: thread per (node,head)
    {
        int gw = gw0 + tid;
        if (gw < NPAIRS) {
            int node = gw >> 2;
            int head = gw & 3;
            int start = g_off[node];
            int end   = g_off[node + 1];
            int deg = end - start;

            ull key[8];
            #pragma unroll
            for (int r = 0; r < 8; r++) {
                ull kv = 0ull;
                if (r < deg) {
                    int c = g_col[start + r];
                    uint32_t u = g_usk[c * 4 + head];
                    kv = ((ull)u << 32) | (unsigned)c;
                }
                key[r] = kv;
            }
            CSWAP(0,1) CSWAP(2,3) CSWAP(4,5) CSWAP(6,7)
            CSWAP(0,2) CSWAP(1,3) CSWAP(4,6) CSWAP(5,7)
            CSWAP(1,2) CSWAP(5,6)
            CSWAP(0,4) CSWAP(1,5) CSWAP(2,6) CSWAP(3,7)
            CSWAP(2,4) CSWAP(3,5)
            CSWAP(1,2) CSWAP(3,4) CSWAP(5,6)

            // tail in batches of 8: cols (coalesced), then keys (MLP=8), then inserts
            int i = start + 8;
            while (i < end) {
                int m = end - i;
                int cc[8];
                uint32_t uu[8];
                #pragma unroll
                for (int r = 0; r < 8; r++)
                    cc[r] = (r < m) ? g_col[i + r] : 0;
                #pragma unroll
                for (int r = 0; r < 8; r++)
                    uu[r] = (r < m) ? __ldg(&g_usk[cc[r] * 4 + head]) : 0u;
                #pragma unroll
                for (int r = 0; r < 8; r++) {
                    if (r < m) {
                        ull kv = ((ull)uu[r] << 32) | (unsigned)cc[r];
                        if (kv > key[7]) { key[7] = kv; BUBBLE() }
                    }
                }
                i += 8;
            }

            int k = min(deg, TOPK);
            float si = g_si[gw];
            float sc[TOPK];
            #pragma unroll
            for (int r = 0; r < TOPK; r++) {
                unsigned u = (unsigned)(key[r] >> 32);
                u ^= (~((unsigned)((int)u >> 31))) | 0x80000000u;  // inverse map
                float s = si + __uint_as_float(u);
                sc[r] = (s > 0.f) ? s : 0.2f * s;                  // leaky
            }
            float maxe = sc[0];
            float p[TOPK];
            float sum = 0.f;
            #pragma unroll
            for (int r = 0; r < TOPK; r++) {
                float e = (r < k) ? __expf(sc[r] - maxe) : 0.f;
                p[r] = e;
                sum += e;
            }
            float inv = 1.f / sum;
            #pragma unroll
            for (int r = 0; r < TOPK; r++) {
                salpha[tid][r] = p[r] * inv;
                scol[tid][r]   = (int)(unsigned)(key[r] & 0xffffffffull);
            }
        } else {
            #pragma unroll
            for (int r = 0; r < TOPK; r++) { salpha[tid][r] = 0.f; scol[tid][r] = 0; }
        }
    }
    __syncthreads();

    // ---- phase 2: warp per pair
    int wid = tid >> 5, lane = tid & 31;
    for (int p = 0; p < 32; p++) {
        int lp = wid * 32 + p;
        int gw = gw0 + lp;
        if (gw >= NPAIRS) break;
        int node = gw >> 2;
        int head = gw & 3;
        float acc = 0.f;
        #pragma unroll
        for (int r = 0; r < TOPK; r++) {
            float a = salpha[lp][r];
            int   c = scol[lp][r];
            acc += a * __ldg(&g_h[c * 128 + head * OUT_CH + lane]);
        }
        out[node * 128 + head * OUT_CH + lane] = (acc > 0.f) ? acc : expm1f(acc);
    }
}

// ---------------- launch: 5 launches, single stream -------------------------
extern "C" void kernel_launch(void* const* d_in, const int* in_sizes, int n_in,
                              void* d_out, int out_size) {
    const float* x   = (const float*)d_in[0];
    const float* W   = (const float*)d_in[1];
    const float* att = (const float*)d_in[2];
    const int*   ei  = (const int*)d_in[3];
    float* out = (float*)d_out;

    k_histprep<<<HIST_BLOCKS + 64, 256>>>(ei, W, att);                 // 0
    k_scan1<<<NB_SCAN, 1024>>>();                                      // 1
    k_scan3<<<NB_SCAN, 1024>>>();                                      // 2
    k_fused<<<GEMM_BLOCKS + SCORES_BLOCKS + SCAT_BLOCKS, 256>>>(x, ei);// 3 (profiled)
    k_topkagg<<<(NPAIRS + 255) / 256, 256>>>(out);                     // 4
}

// round 16
// speedup vs baseline: 1.4550x; 1.0140x over previous
#include <cuda_runtime.h>
#include <cuda_bf16.h>
#include <math.h>
#include <stdint.h>

#define N_NODES 50000
#define N_EDGES 800000
#define ET (N_EDGES + N_NODES)
#define HEADS 4
#define OUT_CH 32
#define TOPK 8
#define NPAIRS (N_NODES * HEADS)
#define NB_SCAN ((N_NODES + 1023) / 1024)
typedef unsigned long long ull;

#define GEMM_BLOCKS   ((N_NODES + 127) / 128)          // 391
#define SCORES_BLOCKS ((N_NODES + 63) / 64)            // 782
#define SCAT_BLOCKS   ((ET + 255) / 256)               // 3321
#define HIST_BLOCKS   ((N_EDGES / 4 + 255) / 256)      // 782

// ---------------- scratch ----------------
__device__ __align__(16) float g_h[N_NODES * 128];           // 25.6 MB
__device__ __align__(16) float g_si[NPAIRS];
__device__ __align__(16) uint32_t g_usk[NPAIRS];             // monotone(sj) keys
__device__ int   g_deg[N_NODES + 1];     // .bss zero; reset by k_scan each run
__device__ int   g_off[N_NODES + 1];
__device__ int   g_cur[N_NODES];
__device__ int   g_col[ET];
__device__ int   g_bsum[NB_SCAN];        // 0 = not ready; reset by histprep
__device__ __align__(16) __nv_bfloat16 g_wth[128 * 128];     // W^T hi [n][k]
__device__ __align__(16) __nv_bfloat16 g_wtl[128 * 128];     // W^T lo [n][k]
__device__ __align__(16) float g_a2[128 * 8];                // W @ att combos

// ---------------- fused hist + prep (+ bsum reset) ----------------
__global__ void k_histprep(const int* __restrict__ ei,
                           const float* __restrict__ W,
                           const float* __restrict__ att) {
    int b = blockIdx.x;
    int tid = threadIdx.x;
    if (b < HIST_BLOCKS) {
        int e = (b * 256 + tid) * 4;
        if (e < N_EDGES) {
            int4 v = *(const int4*)&ei[e];
            atomicAdd(&g_deg[v.x], 1);
            atomicAdd(&g_deg[v.y], 1);
            atomicAdd(&g_deg[v.z], 1);
            atomicAdd(&g_deg[v.w], 1);
        }
    } else {
        int t = (b - HIST_BLOCKS) * 256 + tid;
        if (t < NB_SCAN) g_bsum[t] = 0;     // ready-flags for k_scan lookback
        if (t < 16384) {
            int n = t >> 7, k = t & 127;
            float w = W[k * 128 + n];
            __nv_bfloat16 hi = __float2bfloat16(w);
            float lo = w - __bfloat162float(hi);
            g_wth[n * 128 + k] = hi;
            g_wtl[n * 128 + k] = __float2bfloat16(lo);
        }
        if (t < 1024) {
            int k = t >> 3, j = t & 7;
            int h = j & 3, part = j >> 2;
            float s = 0.f;
            #pragma unroll
            for (int c = 0; c < 32; c++)
                s += W[k * 128 + h * 32 + c] * att[h * 64 + part * 32 + c];
            g_a2[k * 8 + j] = s;
        }
    }
}

// ---------------- single-kernel scan (decoupled lookback) ----------------
// 49 blocks << 148 SMs -> all resident; flag = block total (>=848, so 0 = unset).
__global__ void k_scan() {
    __shared__ int wsum[32];
    __shared__ int sh_carry;
    int tid = threadIdx.x;
    int lane = tid & 31, w = tid >> 5;
    int b = blockIdx.x;
    int i = b * 1024 + tid;
    int v = 0;
    if (i < N_NODES) {
        v = g_deg[i] + 1;       // +1 self-loop
        g_deg[i] = 0;           // reset for next graph replay
        g_cur[i] = 0;
    }
    int s = v;
    #pragma unroll
    for (int o = 1; o < 32; o <<= 1) {
        int t = __shfl_up_sync(0xffffffffu, s, o);
        if (lane >= o) s += t;
    }
    if (lane == 31) wsum[w] = s;
    __syncthreads();
    if (w == 0) {
        int t = wsum[lane];
        #pragma unroll
        for (int o = 1; o < 32; o <<= 1) {
            int u = __shfl_up_sync(0xffffffffu, t, o);
            if (lane >= o) t += u;
        }
        wsum[lane] = t;                                   // inclusive warp-sums
        if (lane == 31) atomicExch(&g_bsum[b], t);        // publish block total
    }
    __syncthreads();
    // lookback: sum all predecessor block totals (poll until published)
    if (w == 0) {
        int sum = 0;
        for (int j = lane; j < b; j += 32) {
            int val;
            do { val = atomicAdd(&g_bsum[j], 0); } while (val == 0);
            sum += val;
        }
        #pragma unroll
        for (int o = 16; o; o >>= 1) sum += __shfl_xor_sync(0xffffffffu, sum, o);
        if (lane == 0) sh_carry = sum;
    }
    __syncthreads();
    int carry = ((w > 0) ? wsum[w - 1] : 0) + sh_carry;
    if (i < N_NODES) g_off[i] = s - v + carry;
    if (i == 0) g_off[N_NODES] = ET;
}

// ---------------- fused gemm | scores | scatter ----------------
#define KP 40

__device__ __forceinline__ void hmma(float* c, const uint32_t* a,
                                     uint32_t b0, uint32_t b1) {
    asm volatile(
        "mma.sync.aligned.m16n8k16.row.col.f32.bf16.bf16.f32 "
        "{%0,%1,%2,%3}, {%4,%5,%6,%7}, {%8,%9}, {%0,%1,%2,%3};"
        : "+f"(c[0]), "+f"(c[1]), "+f"(c[2]), "+f"(c[3])
        : "r"(a[0]), "r"(a[1]), "r"(a[2]), "r"(a[3]), "r"(b0), "r"(b1));
}

#define LDSM4(R, addr) \
    asm volatile("ldmatrix.sync.aligned.m8n8.x4.shared.b16 {%0,%1,%2,%3}, [%4];" \
        : "=r"((R)[0]), "=r"((R)[1]), "=r"((R)[2]), "=r"((R)[3]) : "r"(addr))

__device__ void gemm_body(int bs, const float* __restrict__ x, char* sb) {
    __nv_bfloat16 (*sAh)[KP] = (__nv_bfloat16(*)[KP])(sb);
    __nv_bfloat16 (*sAl)[KP] = (__nv_bfloat16(*)[KP])(sb + 10240);
    __nv_bfloat16 (*sBh)[KP] = (__nv_bfloat16(*)[KP])(sb + 20480);
    __nv_bfloat16 (*sBl)[KP] = (__nv_bfloat16(*)[KP])(sb + 30720);

    int tid = threadIdx.x;
    int wid = tid >> 5, lane = tid & 31;
    int m0 = bs * 128;
    int rb = (wid & 3) * 32;
    int nb = (wid >> 2) * 64;

    float acc[2][8][4];
    #pragma unroll
    for (int mt = 0; mt < 2; mt++)
        #pragma unroll
        for (int nt = 0; nt < 8; nt++)
            #pragma unroll
            for (int q = 0; q < 4; q++) acc[mt][nt][q] = 0.f;

    int tsub = lane >> 3;
    int trow = lane & 7;

    for (int st = 0; st < 4; st++) {
        int k0 = st * 32;
        #pragma unroll
        for (int it = 0; it < 2; it++) {
            int idx = tid + it * 256;
            int row = idx >> 2;
            int c0 = (idx & 3) * 8;
            int rr = m0 + row;
            float4 v0 = make_float4(0.f, 0.f, 0.f, 0.f), v1 = v0;
            if (rr < N_NODES) {
                v0 = *(const float4*)&x[rr * 128 + k0 + c0];
                v1 = *(const float4*)&x[rr * 128 + k0 + c0 + 4];
            }
            float vs[8] = {v0.x, v0.y, v0.z, v0.w, v1.x, v1.y, v1.z, v1.w};
            uint32_t hw[4], lw[4];
            #pragma unroll
            for (int q = 0; q < 4; q++) {
                __nv_bfloat16 h0 = __float2bfloat16(vs[2 * q]);
                __nv_bfloat16 h1 = __float2bfloat16(vs[2 * q + 1]);
                float l0 = vs[2 * q] - __bfloat162float(h0);
                float l1 = vs[2 * q + 1] - __bfloat162float(h1);
                hw[q] = (uint32_t)__bfloat16_as_ushort(h0) |
                        ((uint32_t)__bfloat16_as_ushort(h1) << 16);
                lw[q] = (uint32_t)__bfloat16_as_ushort(__float2bfloat16(l0)) |
                        ((uint32_t)__bfloat16_as_ushort(__float2bfloat16(l1)) << 16);
            }
            *(uint4*)&sAh[row][c0] = make_uint4(hw[0], hw[1], hw[2], hw[3]);
            *(uint4*)&sAl[row][c0] = make_uint4(lw[0], lw[1], lw[2], lw[3]);
            *(uint4*)&sBh[row][c0] = *(const uint4*)&g_wth[row * 128 + k0 + c0];
            *(uint4*)&sBl[row][c0] = *(const uint4*)&g_wtl[row * 128 + k0 + c0];
        }
        __syncthreads();

        #pragma unroll
        for (int ks = 0; ks < 2; ks++) {
            int ck = ks * 16;
            uint32_t Ah[2][4], Al[2][4];
            #pragma unroll
            for (int mt = 0; mt < 2; mt++) {
                int r = rb + mt * 16 + ((tsub & 1) << 3) + trow;
                int c = ck + ((tsub >> 1) << 3);
                LDSM4(Ah[mt], (uint32_t)__cvta_generic_to_shared(&sAh[r][c]));
                LDSM4(Al[mt], (uint32_t)__cvta_generic_to_shared(&sAl[r][c]));
            }
            #pragma unroll
            for (int np = 0; np < 4; np++) {
                int n = nb + np * 16 + ((tsub >> 1) << 3) + trow;
                int c = ck + ((tsub & 1) << 3);
                uint32_t Bh[4], Bl[4];
                LDSM4(Bh, (uint32_t)__cvta_generic_to_shared(&sBh[n][c]));
                LDSM4(Bl, (uint32_t)__cvta_generic_to_shared(&sBl[n][c]));
                #pragma unroll
                for (int mt = 0; mt < 2; mt++) {
                    hmma(acc[mt][2 * np],     Ah[mt], Bh[0], Bh[1]);
                    hmma(acc[mt][2 * np],     Ah[mt], Bl[0], Bl[1]);
                    hmma(acc[mt][2 * np],     Al[mt], Bh[0], Bh[1]);
                    hmma(acc[mt][2 * np + 1], Ah[mt], Bh[2], Bh[3]);
                    hmma(acc[mt][2 * np + 1], Ah[mt], Bl[2], Bl[3]);
                    hmma(acc[mt][2 * np + 1], Al[mt], Bh[2], Bh[3]);
                }
            }
        }
        __syncthreads();
    }

    #pragma unroll
    for (int mt = 0; mt < 2; mt++) {
        int r0 = m0 + rb + mt * 16 + (lane >> 2);
        #pragma unroll
        for (int nt = 0; nt < 8; nt++) {
            int col = nb + nt * 8 + (lane & 3) * 2;
            if (r0 < N_NODES)
                *(float2*)&g_h[r0 * 128 + col] =
                    make_float2(acc[mt][nt][0], acc[mt][nt][1]);
            if (r0 + 8 < N_NODES)
                *(float2*)&g_h[(r0 + 8) * 128 + col] =
                    make_float2(acc[mt][nt][2], acc[mt][nt][3]);
        }
    }
}

__device__ void scores_body(int bs, const float* __restrict__ x, char* sb) {
    float (*srow)[132] = (float(*)[132])sb;
    int tid = threadIdx.x;
    int w = tid >> 5, lane = tid & 31;
    int j = lane >> 2, rot = lane & 3;

    float4 areg[8];
    #pragma unroll
    for (int i = 0; i < 8; i++) {
        int kb = rot * 32 + ((i + 2 * rot) & 7) * 4;
        areg[i].x = g_a2[(kb + 0) * 8 + j];
        areg[i].y = g_a2[(kb + 1) * 8 + j];
        areg[i].z = g_a2[(kb + 2) * 8 + j];
        areg[i].w = g_a2[(kb + 3) * 8 + j];
    }

    int base = (bs * 8 + w) * 8;

    float4 xv[8];
    #pragma unroll
    for (int n = 0; n < 8; n++) {
        int node = base + n;
        xv[n] = (node < N_NODES) ? *(const float4*)&x[node * 128 + lane * 4]
                                 : make_float4(0.f, 0.f, 0.f, 0.f);
    }

    #pragma unroll
    for (int n = 0; n < 8; n++) {
        int node = base + n;
        if (node >= N_NODES) break;
        *(float4*)&srow[w][lane * 4] = xv[n];
        __syncwarp();
        float acc = 0.f;
        #pragma unroll
        for (int i = 0; i < 8; i++) {
            const float4 v = *(const float4*)&srow[w][rot * 32 + ((i + 2 * rot) & 7) * 4];
            acc += v.x * areg[i].x + v.y * areg[i].y + v.z * areg[i].z + v.w * areg[i].w;
        }
        acc += __shfl_xor_sync(0xffffffffu, acc, 1);
        acc += __shfl_xor_sync(0xffffffffu, acc, 2);
        if (rot == 0) {
            if (j < 4) {
                g_si[node * 4 + j] = acc;
            } else {
                unsigned u = __float_as_uint(acc);
                u ^= (unsigned)((int)u >> 31) | 0x80000000u;   // monotone map
                g_usk[node * 4 + (j - 4)] = u;
            }
        }
        __syncwarp();
    }
}

__device__ void scatter_body(int bs, const int* __restrict__ ei) {
    int idx = bs * 256 + threadIdx.x;
    if (idx >= ET) return;
    int r, c;
    if (idx < N_EDGES) { r = ei[idx]; c = ei[N_EDGES + idx]; }
    else               { r = idx - N_EDGES; c = r; }
    int p = g_off[r] + atomicAdd(&g_cur[r], 1);
    g_col[p] = c;
}

__global__ void __launch_bounds__(256)
k_fused(const float* __restrict__ x, const int* __restrict__ ei) {
    __shared__ __align__(16) char sbuf[40960];
    int b = blockIdx.x;
    if (b < GEMM_BLOCKS)                      gemm_body(b, x, sbuf);
    else if (b < GEMM_BLOCKS + SCORES_BLOCKS) scores_body(b - GEMM_BLOCKS, x, sbuf);
    else                                      scatter_body(b - GEMM_BLOCKS - SCORES_BLOCKS, ei);
}

// ---------------- fused top-k + softmax + aggregate + ELU ------------------
#define CSWAP(a, b) { ull _x = key[a], _y = key[b]; \
                      key[a] = (_x > _y) ? _x : _y; key[b] = (_x > _y) ? _y : _x; }
#define BUBBLE() { CSWAP(6,7) CSWAP(5,6) CSWAP(4,5) CSWAP(3,4) \
                   CSWAP(2,3) CSWAP(1,2) CSWAP(0,1) }

__global__ void __launch_bounds__(256) k_topkagg(float* __restrict__ out) {
    __shared__ float salpha[256][TOPK];
    __shared__ int   scol[256][TOPK];

    int tid = threadIdx.x;
    int gw0 = blockIdx.x * 256;

    // ---- phase 1: thread per (node,head)
    {
        int gw = gw0 + tid;
        if (gw < NPAIRS) {
            int node = gw >> 2;
            int head = gw & 3;
            int start = g_off[node];
            int end   = g_off[node + 1];
            int deg = end - start;

            ull key[8];
            #pragma unroll
            for (int r = 0; r < 8; r++) {
                ull kv = 0ull;
                if (r < deg) {
                    int c = g_col[start + r];
                    uint32_t u = g_usk[c * 4 + head];
                    kv = ((ull)u << 32) | (unsigned)c;
                }
                key[r] = kv;
            }
            CSWAP(0,1) CSWAP(2,3) CSWAP(4,5) CSWAP(6,7)
            CSWAP(0,2) CSWAP(1,3) CSWAP(4,6) CSWAP(5,7)
            CSWAP(1,2) CSWAP(5,6)
            CSWAP(0,4) CSWAP(1,5) CSWAP(2,6) CSWAP(3,7)
            CSWAP(2,4) CSWAP(3,5)
            CSWAP(1,2) CSWAP(3,4) CSWAP(5,6)

            int i = start + 8;
            while (i < end) {
                int m = end - i;
                int cc[8];
                uint32_t uu[8];
                #pragma unroll
                for (int r = 0; r < 8; r++)
                    cc[r] = (r < m) ? g_col[i + r] : 0;
                #pragma unroll
                for (int r = 0; r < 8; r++)
                    uu[r] = (r < m) ? __ldg(&g_usk[cc[r] * 4 + head]) : 0u;
                #pragma unroll
                for (int r = 0; r < 8; r++) {
                    if (r < m) {
                        ull kv = ((ull)uu[r] << 32) | (unsigned)cc[r];
                        if (kv > key[7]) { key[7] = kv; BUBBLE() }
                    }
                }
                i += 8;
            }

            int k = min(deg, TOPK);
            float si = g_si[gw];
            float sc[TOPK];
            #pragma unroll
            for (int r = 0; r < TOPK; r++) {
                unsigned u = (unsigned)(key[r] >> 32);
                u ^= (~((unsigned)((int)u >> 31))) | 0x80000000u;  // inverse map
                float s = si + __uint_as_float(u);
                sc[r] = (s > 0.f) ? s : 0.2f * s;                  // leaky
            }
            float maxe = sc[0];
            float p[TOPK];
            float sum = 0.f;
            #pragma unroll
            for (int r = 0; r < TOPK; r++) {
                float e = (r < k) ? __expf(sc[r] - maxe) : 0.f;
                p[r] = e;
                sum += e;
            }
            float inv = 1.f / sum;
            #pragma unroll
            for (int r = 0; r < TOPK; r++) {
                salpha[tid][r] = p[r] * inv;
                scol[tid][r]   = (int)(unsigned)(key[r] & 0xffffffffull);
            }
        } else {
            #pragma unroll
            for (int r = 0; r < TOPK; r++) { salpha[tid][r] = 0.f; scol[tid][r] = 0; }
        }
    }
    __syncthreads();

    // ---- phase 2: warp per pair
    int wid = tid >> 5, lane = tid & 31;
    for (int p = 0; p < 32; p++) {
        int lp = wid * 32 + p;
        int gw = gw0 + lp;
        if (gw >= NPAIRS) break;
        int node = gw >> 2;
        int head = gw & 3;
        float acc = 0.f;
        #pragma unroll
        for (int r = 0; r < TOPK; r++) {
            float a = salpha[lp][r];
            int   c = scol[lp][r];
            acc += a * __ldg(&g_h[c * 128 + head * OUT_CH + lane]);
        }
        out[node * 128 + head * OUT_CH + lane] = (acc > 0.f) ? acc : expm1f(acc);
    }
}

// ---------------- launch: 4 launches, single stream -------------------------
extern "C" void kernel_launch(void* const* d_in, const int* in_sizes, int n_in,
                              void* d_out, int out_size) {
    const float* x   = (const float*)d_in[0];
    const float* W   = (const float*)d_in[1];
    const float* att = (const float*)d_in[2];
    const int*   ei  = (const int*)d_in[3];
    float* out = (float*)d_out;

    k_histprep<<<HIST_BLOCKS + 64, 256>>>(ei, W, att);                 // 0
    k_scan<<<NB_SCAN, 1024>>>();                                       // 1
    k_fused<<<GEMM_BLOCKS + SCORES_BLOCKS + SCAT_BLOCKS, 256>>>(x, ei);// 2
    k_topkagg<<<(NPAIRS + 255) / 256, 256>>>(out);                     // 3 (profiled)
}

// round 17
// speedup vs baseline: 1.4653x; 1.0071x over previous
#include <cuda_runtime.h>
#include <cuda_bf16.h>
#include <math.h>
#include <stdint.h>

#define N_NODES 50000
#define N_EDGES 800000
#define ET (N_EDGES + N_NODES)
#define HEADS 4
#define OUT_CH 32
#define TOPK 8
#define NPAIRS (N_NODES * HEADS)
#define NB_SCAN ((N_NODES + 1023) / 1024)
typedef unsigned long long ull;

#define GEMM_BLOCKS   ((N_NODES + 127) / 128)          // 391
#define SCORES_BLOCKS ((N_NODES + 63) / 64)            // 782
#define SCAT_BLOCKS   ((ET + 255) / 256)               // 3321
#define HIST_BLOCKS   ((N_EDGES / 4 + 255) / 256)      // 782

// ---------------- scratch ----------------
__device__ __align__(16) float g_h[N_NODES * 128];           // 25.6 MB
__device__ __align__(16) float g_si[NPAIRS];
__device__ __align__(16) uint32_t g_usk[NPAIRS];             // monotone(sj) keys
__device__ int   g_deg[N_NODES + 1];     // .bss zero; reset by k_scan each run
__device__ int   g_off[N_NODES + 1];
__device__ int   g_cur[N_NODES];
__device__ int   g_col[ET];
__device__ int   g_bsum[NB_SCAN];        // 0 = not ready; reset by histprep
__device__ __align__(16) float g_ta[NPAIRS * TOPK];          // alphas, 6.4 MB
__device__ __align__(16) int   g_tc[NPAIRS * TOPK];          // columns, 6.4 MB
__device__ __align__(16) __nv_bfloat16 g_wth[128 * 128];     // W^T hi [n][k]
__device__ __align__(16) __nv_bfloat16 g_wtl[128 * 128];     // W^T lo [n][k]
__device__ __align__(16) float g_a2[128 * 8];                // W @ att combos

// ---------------- fused hist + prep (+ bsum reset) ----------------
__global__ void k_histprep(const int* __restrict__ ei,
                           const float* __restrict__ W,
                           const float* __restrict__ att) {
    int b = blockIdx.x;
    int tid = threadIdx.x;
    if (b < HIST_BLOCKS) {
        int e = (b * 256 + tid) * 4;
        if (e < N_EDGES) {
            int4 v = *(const int4*)&ei[e];
            atomicAdd(&g_deg[v.x], 1);
            atomicAdd(&g_deg[v.y], 1);
            atomicAdd(&g_deg[v.z], 1);
            atomicAdd(&g_deg[v.w], 1);
        }
    } else {
        int t = (b - HIST_BLOCKS) * 256 + tid;
        if (t < NB_SCAN) g_bsum[t] = 0;     // ready-flags for k_scan lookback
        if (t < 16384) {
            int n = t >> 7, k = t & 127;
            float w = W[k * 128 + n];
            __nv_bfloat16 hi = __float2bfloat16(w);
            float lo = w - __bfloat162float(hi);
            g_wth[n * 128 + k] = hi;
            g_wtl[n * 128 + k] = __float2bfloat16(lo);
        }
        if (t < 1024) {
            int k = t >> 3, j = t & 7;
            int h = j & 3, part = j >> 2;
            float s = 0.f;
            #pragma unroll
            for (int c = 0; c < 32; c++)
                s += W[k * 128 + h * 32 + c] * att[h * 64 + part * 32 + c];
            g_a2[k * 8 + j] = s;
        }
    }
}

// ---------------- single-kernel scan (decoupled lookback) ----------------
__global__ void k_scan() {
    __shared__ int wsum[32];
    __shared__ int sh_carry;
    int tid = threadIdx.x;
    int lane = tid & 31, w = tid >> 5;
    int b = blockIdx.x;
    int i = b * 1024 + tid;
    int v = 0;
    if (i < N_NODES) {
        v = g_deg[i] + 1;       // +1 self-loop
        g_deg[i] = 0;           // reset for next graph replay
        g_cur[i] = 0;
    }
    int s = v;
    #pragma unroll
    for (int o = 1; o < 32; o <<= 1) {
        int t = __shfl_up_sync(0xffffffffu, s, o);
        if (lane >= o) s += t;
    }
    if (lane == 31) wsum[w] = s;
    __syncthreads();
    if (w == 0) {
        int t = wsum[lane];
        #pragma unroll
        for (int o = 1; o < 32; o <<= 1) {
            int u = __shfl_up_sync(0xffffffffu, t, o);
            if (lane >= o) t += u;
        }
        wsum[lane] = t;
        if (lane == 31) atomicExch(&g_bsum[b], t);        // publish block total
    }
    __syncthreads();
    if (w == 0) {
        int sum = 0;
        for (int j = lane; j < b; j += 32) {
            int val;
            do { val = atomicAdd(&g_bsum[j], 0); } while (val == 0);
            sum += val;
        }
        #pragma unroll
        for (int o = 16; o; o >>= 1) sum += __shfl_xor_sync(0xffffffffu, sum, o);
        if (lane == 0) sh_carry = sum;
    }
    __syncthreads();
    int carry = ((w > 0) ? wsum[w - 1] : 0) + sh_carry;
    if (i < N_NODES) g_off[i] = s - v + carry;
    if (i == 0) g_off[N_NODES] = ET;
}

// ---------------- fused gemm | scores | scatter ----------------
#define KP 40

__device__ __forceinline__ void hmma(float* c, const uint32_t* a,
                                     uint32_t b0, uint32_t b1) {
    asm volatile(
        "mma.sync.aligned.m16n8k16.row.col.f32.bf16.bf16.f32 "
        "{%0,%1,%2,%3}, {%4,%5,%6,%7}, {%8,%9}, {%0,%1,%2,%3};"
        : "+f"(c[0]), "+f"(c[1]), "+f"(c[2]), "+f"(c[3])
        : "r"(a[0]), "r"(a[1]), "r"(a[2]), "r"(a[3]), "r"(b0), "r"(b1));
}

#define LDSM4(R, addr) \
    asm volatile("ldmatrix.sync.aligned.m8n8.x4.shared.b16 {%0,%1,%2,%3}, [%4];" \
        : "=r"((R)[0]), "=r"((R)[1]), "=r"((R)[2]), "=r"((R)[3]) : "r"(addr))

__device__ void gemm_body(int bs, const float* __restrict__ x, char* sb) {
    __nv_bfloat16 (*sAh)[KP] = (__nv_bfloat16(*)[KP])(sb);
    __nv_bfloat16 (*sAl)[KP] = (__nv_bfloat16(*)[KP])(sb + 10240);
    __nv_bfloat16 (*sBh)[KP] = (__nv_bfloat16(*)[KP])(sb + 20480);
    __nv_bfloat16 (*sBl)[KP] = (__nv_bfloat16(*)[KP])(sb + 30720);

    int tid = threadIdx.x;
    int wid = tid >> 5, lane = tid & 31;
    int m0 = bs * 128;
    int rb = (wid & 3) * 32;
    int nb = (wid >> 2) * 64;

    float acc[2][8][4];
    #pragma unroll
    for (int mt = 0; mt < 2; mt++)
        #pragma unroll
        for (int nt = 0; nt < 8; nt++)
            #pragma unroll
            for (int q = 0; q < 4; q++) acc[mt][nt][q] = 0.f;

    int tsub = lane >> 3;
    int trow = lane & 7;

    for (int st = 0; st < 4; st++) {
        int k0 = st * 32;
        #pragma unroll
        for (int it = 0; it < 2; it++) {
            int idx = tid + it * 256;
            int row = idx >> 2;
            int c0 = (idx & 3) * 8;
            int rr = m0 + row;
            float4 v0 = make_float4(0.f, 0.f, 0.f, 0.f), v1 = v0;
            if (rr < N_NODES) {
                v0 = *(const float4*)&x[rr * 128 + k0 + c0];
                v1 = *(const float4*)&x[rr * 128 + k0 + c0 + 4];
            }
            float vs[8] = {v0.x, v0.y, v0.z, v0.w, v1.x, v1.y, v1.z, v1.w};
            uint32_t hw[4], lw[4];
            #pragma unroll
            for (int q = 0; q < 4; q++) {
                __nv_bfloat16 h0 = __float2bfloat16(vs[2 * q]);
                __nv_bfloat16 h1 = __float2bfloat16(vs[2 * q + 1]);
                float l0 = vs[2 * q] - __bfloat162float(h0);
                float l1 = vs[2 * q + 1] - __bfloat162float(h1);
                hw[q] = (uint32_t)__bfloat16_as_ushort(h0) |
                        ((uint32_t)__bfloat16_as_ushort(h1) << 16);
                lw[q] = (uint32_t)__bfloat16_as_ushort(__float2bfloat16(l0)) |
                        ((uint32_t)__bfloat16_as_ushort(__float2bfloat16(l1)) << 16);
            }
            *(uint4*)&sAh[row][c0] = make_uint4(hw[0], hw[1], hw[2], hw[3]);
            *(uint4*)&sAl[row][c0] = make_uint4(lw[0], lw[1], lw[2], lw[3]);
            *(uint4*)&sBh[row][c0] = *(const uint4*)&g_wth[row * 128 + k0 + c0];
            *(uint4*)&sBl[row][c0] = *(const uint4*)&g_wtl[row * 128 + k0 + c0];
        }
        __syncthreads();

        #pragma unroll
        for (int ks = 0; ks < 2; ks++) {
            int ck = ks * 16;
            uint32_t Ah[2][4], Al[2][4];
            #pragma unroll
            for (int mt = 0; mt < 2; mt++) {
                int r = rb + mt * 16 + ((tsub & 1) << 3) + trow;
                int c = ck + ((tsub >> 1) << 3);
                LDSM4(Ah[mt], (uint32_t)__cvta_generic_to_shared(&sAh[r][c]));
                LDSM4(Al[mt], (uint32_t)__cvta_generic_to_shared(&sAl[r][c]));
            }
            #pragma unroll
            for (int np = 0; np < 4; np++) {
                int n = nb + np * 16 + ((tsub >> 1) << 3) + trow;
                int c = ck + ((tsub & 1) << 3);
                uint32_t Bh[4], Bl[4];
                LDSM4(Bh, (uint32_t)__cvta_generic_to_shared(&sBh[n][c]));
                LDSM4(Bl, (uint32_t)__cvta_generic_to_shared(&sBl[n][c]));
                #pragma unroll
                for (int mt = 0; mt < 2; mt++) {
                    hmma(acc[mt][2 * np],     Ah[mt], Bh[0], Bh[1]);
                    hmma(acc[mt][2 * np],     Ah[mt], Bl[0], Bl[1]);
                    hmma(acc[mt][2 * np],     Al[mt], Bh[0], Bh[1]);
                    hmma(acc[mt][2 * np + 1], Ah[mt], Bh[2], Bh[3]);
                    hmma(acc[mt][2 * np + 1], Ah[mt], Bl[2], Bl[3]);
                    hmma(acc[mt][2 * np + 1], Al[mt], Bh[2], Bh[3]);
                }
            }
        }
        __syncthreads();
    }

    #pragma unroll
    for (int mt = 0; mt < 2; mt++) {
        int r0 = m0 + rb + mt * 16 + (lane >> 2);
        #pragma unroll
        for (int nt = 0; nt < 8; nt++) {
            int col = nb + nt * 8 + (lane & 3) * 2;
            if (r0 < N_NODES)
                *(float2*)&g_h[r0 * 128 + col] =
                    make_float2(acc[mt][nt][0], acc[mt][nt][1]);
            if (r0 + 8 < N_NODES)
                *(float2*)&g_h[(r0 + 8) * 128 + col] =
                    make_float2(acc[mt][nt][2], acc[mt][nt][3]);
        }
    }
}

__device__ void scores_body(int bs, const float* __restrict__ x, char* sb) {
    float (*srow)[132] = (float(*)[132])sb;
    int tid = threadIdx.x;
    int w = tid >> 5, lane = tid & 31;
    int j = lane >> 2, rot = lane & 3;

    float4 areg[8];
    #pragma unroll
    for (int i = 0; i < 8; i++) {
        int kb = rot * 32 + ((i + 2 * rot) & 7) * 4;
        areg[i].x = g_a2[(kb + 0) * 8 + j];
        areg[i].y = g_a2[(kb + 1) * 8 + j];
        areg[i].z = g_a2[(kb + 2) * 8 + j];
        areg[i].w = g_a2[(kb + 3) * 8 + j];
    }

    int base = (bs * 8 + w) * 8;

    float4 xv[8];
    #pragma unroll
    for (int n = 0; n < 8; n++) {
        int node = base + n;
        xv[n] = (node < N_NODES) ? *(const float4*)&x[node * 128 + lane * 4]
                                 : make_float4(0.f, 0.f, 0.f, 0.f);
    }

    #pragma unroll
    for (int n = 0; n < 8; n++) {
        int node = base + n;
        if (node >= N_NODES) break;
        *(float4*)&srow[w][lane * 4] = xv[n];
        __syncwarp();
        float acc = 0.f;
        #pragma unroll
        for (int i = 0; i < 8; i++) {
            const float4 v = *(const float4*)&srow[w][rot * 32 + ((i + 2 * rot) & 7) * 4];
            acc += v.x * areg[i].x + v.y * areg[i].y + v.z * areg[i].z + v.w * areg[i].w;
        }
        acc += __shfl_xor_sync(0xffffffffu, acc, 1);
        acc += __shfl_xor_sync(0xffffffffu, acc, 2);
        if (rot == 0) {
            if (j < 4) {
                g_si[node * 4 + j] = acc;
            } else {
                unsigned u = __float_as_uint(acc);
                u ^= (unsigned)((int)u >> 31) | 0x80000000u;   // monotone map
                g_usk[node * 4 + (j - 4)] = u;
            }
        }
        __syncwarp();
    }
}

__device__ void scatter_body(int bs, const int* __restrict__ ei) {
    int idx = bs * 256 + threadIdx.x;
    if (idx >= ET) return;
    int r, c;
    if (idx < N_EDGES) { r = ei[idx]; c = ei[N_EDGES + idx]; }
    else               { r = idx - N_EDGES; c = r; }
    int p = g_off[r] + atomicAdd(&g_cur[r], 1);
    g_col[p] = c;
}

__global__ void __launch_bounds__(256)
k_fused(const float* __restrict__ x, const int* __restrict__ ei) {
    __shared__ __align__(16) char sbuf[40960];
    int b = blockIdx.x;
    if (b < GEMM_BLOCKS)                      gemm_body(b, x, sbuf);
    else if (b < GEMM_BLOCKS + SCORES_BLOCKS) scores_body(b - GEMM_BLOCKS, x, sbuf);
    else                                      scatter_body(b - GEMM_BLOCKS - SCORES_BLOCKS, ei);
}

// ---------------- top-k: thread per (node,head), no block barrier ----------
#define CSWAP(a, b) { ull _x = key[a], _y = key[b]; \
                      key[a] = (_x > _y) ? _x : _y; key[b] = (_x > _y) ? _y : _x; }
#define BUBBLE() { CSWAP(6,7) CSWAP(5,6) CSWAP(4,5) CSWAP(3,4) \
                   CSWAP(2,3) CSWAP(1,2) CSWAP(0,1) }

__global__ void __launch_bounds__(256) k_topk() {
    int gw = blockIdx.x * 256 + threadIdx.x;
    if (gw >= NPAIRS) return;
    int node = gw >> 2;
    int head = gw & 3;
    int start = g_off[node];
    int end   = g_off[node + 1];
    int deg = end - start;

    ull key[8];
    #pragma unroll
    for (int r = 0; r < 8; r++) {
        ull kv = 0ull;
        if (r < deg) {
            int c = g_col[start + r];
            uint32_t u = g_usk[c * 4 + head];
            kv = ((ull)u << 32) | (unsigned)c;
        }
        key[r] = kv;
    }
    CSWAP(0,1) CSWAP(2,3) CSWAP(4,5) CSWAP(6,7)
    CSWAP(0,2) CSWAP(1,3) CSWAP(4,6) CSWAP(5,7)
    CSWAP(1,2) CSWAP(5,6)
    CSWAP(0,4) CSWAP(1,5) CSWAP(2,6) CSWAP(3,7)
    CSWAP(2,4) CSWAP(3,5)
    CSWAP(1,2) CSWAP(3,4) CSWAP(5,6)

    int i = start + 8;
    while (i < end) {
        int m = end - i;
        int cc[8];
        uint32_t uu[8];
        #pragma unroll
        for (int r = 0; r < 8; r++)
            cc[r] = (r < m) ? g_col[i + r] : 0;
        #pragma unroll
        for (int r = 0; r < 8; r++)
            uu[r] = (r < m) ? __ldg(&g_usk[cc[r] * 4 + head]) : 0u;
        #pragma unroll
        for (int r = 0; r < 8; r++) {
            if (r < m) {
                ull kv = ((ull)uu[r] << 32) | (unsigned)cc[r];
                if (kv > key[7]) { key[7] = kv; BUBBLE() }
            }
        }
        i += 8;
    }

    int k = min(deg, TOPK);
    float si = g_si[gw];
    float sc[TOPK];
    #pragma unroll
    for (int r = 0; r < TOPK; r++) {
        unsigned u = (unsigned)(key[r] >> 32);
        u ^= (~((unsigned)((int)u >> 31))) | 0x80000000u;  // inverse map
        float s = si + __uint_as_float(u);
        sc[r] = (s > 0.f) ? s : 0.2f * s;                  // leaky
    }
    float maxe = sc[0];
    float p[TOPK];
    float sum = 0.f;
    #pragma unroll
    for (int r = 0; r < TOPK; r++) {
        float e = (r < k) ? __expf(sc[r] - maxe) : 0.f;
        p[r] = e;
        sum += e;
    }
    float inv = 1.f / sum;
    #pragma unroll
    for (int r = 0; r < TOPK; r++) {
        g_ta[gw * TOPK + r] = p[r] * inv;
        g_tc[gw * TOPK + r] = (int)(unsigned)(key[r] & 0xffffffffull);
    }
}

// ---------------- aggregate: ONE warp per (node,head), max parallelism -----
__global__ void __launch_bounds__(256) k_agg(float* __restrict__ out) {
    int lane = threadIdx.x & 31;
    int gw = (blockIdx.x * blockDim.x + threadIdx.x) >> 5;
    if (gw >= NPAIRS) return;
    int node = gw >> 2;
    int head = gw & 3;

    float a[TOPK];
    int   c[TOPK];
    #pragma unroll
    for (int r = 0; r < TOPK; r++) {
        a[r] = g_ta[gw * TOPK + r];       // broadcast loads
        c[r] = g_tc[gw * TOPK + r];
    }
    float acc = 0.f;
    #pragma unroll
    for (int r = 0; r < TOPK; r++)
        acc += a[r] * __ldg(&g_h[c[r] * 128 + head * OUT_CH + lane]);

    out[node * 128 + head * OUT_CH + lane] = (acc > 0.f) ? acc : expm1f(acc);
}

// ---------------- launch: 5 launches, single stream -------------------------
extern "C" void kernel_launch(void* const* d_in, const int* in_sizes, int n_in,
                              void* d_out, int out_size) {
    const float* x   = (const float*)d_in[0];
    const float* W   = (const float*)d_in[1];
    const float* att = (const float*)d_in[2];
    const int*   ei  = (const int*)d_in[3];
    float* out = (float*)d_out;

    k_histprep<<<HIST_BLOCKS + 64, 256>>>(ei, W, att);                 // 0
    k_scan<<<NB_SCAN, 1024>>>();                                       // 1
    k_fused<<<GEMM_BLOCKS + SCORES_BLOCKS + SCAT_BLOCKS, 256>>>(x, ei);// 2
    k_topk<<<(NPAIRS + 255) / 256, 256>>>();                           // 3 (profiled)
    k_agg<<<(NPAIRS * 32 + 255) / 256, 256>>>(out);                    // 4
}